// round 2
// baseline (speedup 1.0000x reference)
#include <cuda_runtime.h>
#include <math.h>

#define NW 20000
#define NE 30000
#define ER 200000
#define EE 200000
#define H 512
#define MDIM 512
#define ECH 4101
#define OUT_DIM 250
#define NLAYER 4
#define NREL 3
#define SLOPE 0.2f

// ---------------- scratch (device globals; no runtime allocation) ----------------
__device__ float g_hw[NW * H];
__device__ float g_hw2[NW * H];
__device__ float g_h1[NW * H];
__device__ float g_k[NW * H];
__device__ float g_v[NW * H];
__device__ float g_agg[NW * H];
__device__ float g_he[NE * H];
__device__ float g_he2[NE * H];
__device__ float g_agge[NE * H];
__device__ float g_cnt[NE];
__device__ float g_s[NW];
__device__ float g_part[256];
__device__ float g_stat[2];
__device__ float g_q[H];
__device__ float g_gv0[H];
__device__ float g_gv[H];
__device__ float g_gs[H];
__device__ float g_bs[H];
__device__ float g_Wsum[H * H];
__device__ float g_Wgsum[H * H];

__device__ __forceinline__ float leakyf(float v) { return v > 0.f ? v : SLOPE * v; }

// ---------------- GEMM: C = A[MxK] @ B[KxN] (+C if beta) (+bias) (leaky) ----------
__global__ void gemm_kernel(const float* __restrict__ A, const float* __restrict__ B,
                            float* __restrict__ C, int M, int N, int K,
                            const float* __restrict__ bias, int beta, int leaky)
{
    __shared__ float As[16][64];
    __shared__ float Bs[16][64];
    int tid = threadIdx.x;
    int tx = tid & 15, ty = tid >> 4;
    int rowBase = blockIdx.y * 64;
    int colBase = blockIdx.x * 64;
    float acc[4][4] = {};
    for (int k0 = 0; k0 < K; k0 += 16) {
        #pragma unroll
        for (int i = tid; i < 64 * 16; i += 256) {
            int r = i >> 4, c = i & 15;
            int gr = rowBase + r, gc = k0 + c;
            As[c][r] = (gr < M && gc < K) ? A[(long)gr * K + gc] : 0.f;
        }
        #pragma unroll
        for (int i = tid; i < 16 * 64; i += 256) {
            int r = i >> 6, c = i & 63;
            int gr = k0 + r, gc = colBase + c;
            Bs[r][c] = (gr < K && gc < N) ? B[(long)gr * N + gc] : 0.f;
        }
        __syncthreads();
        #pragma unroll
        for (int kk = 0; kk < 16; kk++) {
            float4 a4 = *(const float4*)&As[kk][ty * 4];
            float4 b4 = *(const float4*)&Bs[kk][tx * 4];
            float a[4] = {a4.x, a4.y, a4.z, a4.w};
            float b[4] = {b4.x, b4.y, b4.z, b4.w};
            #pragma unroll
            for (int i = 0; i < 4; i++)
                #pragma unroll
                for (int j = 0; j < 4; j++)
                    acc[i][j] += a[i] * b[j];
        }
        __syncthreads();
    }
    #pragma unroll
    for (int i = 0; i < 4; i++) {
        int r = rowBase + ty * 4 + i;
        if (r >= M) continue;
        #pragma unroll
        for (int j = 0; j < 4; j++) {
            int c = colBase + tx * 4 + j;
            if (c >= N) continue;
            float v = acc[i][j];
            if (beta) v += C[(long)r * N + c];
            if (bias) v += bias[c];
            if (leaky) v = leakyf(v);
            C[(long)r * N + c] = v;
        }
    }
}

// out[1,N] = x[1,K] @ W[K,N] (+bias)
__global__ void vecmat_kernel(const float* __restrict__ x, const float* __restrict__ W,
                              const float* __restrict__ bias, float* __restrict__ out,
                              int K, int N)
{
    int j = blockIdx.x * blockDim.x + threadIdx.x;
    if (j >= N) return;
    float acc = bias ? bias[j] : 0.f;
    for (int k = 0; k < K; k++) acc += x[k] * W[(long)k * N + j];
    out[j] = acc;
}

// s[i] = scale * dot(kmat[i,:], q)
__global__ void scores_kernel(const float* __restrict__ kmat, const float* __restrict__ q,
                              float* __restrict__ s, int n, float scale)
{
    int warp = (blockIdx.x * blockDim.x + threadIdx.x) >> 5;
    int lane = threadIdx.x & 31;
    if (warp >= n) return;
    const float* row = kmat + (long)warp * H;
    float acc = 0.f;
    for (int c = lane; c < H; c += 32) acc += row[c] * q[c];
    #pragma unroll
    for (int o = 16; o > 0; o >>= 1) acc += __shfl_down_sync(0xffffffffu, acc, o);
    if (!lane) s[warp] = acc * scale;
}

__global__ void rmax_part(const float* __restrict__ s, int n, float* __restrict__ part)
{
    __shared__ float sm[256];
    float m = -3.4e38f;
    for (int i = blockIdx.x * 256 + threadIdx.x; i < n; i += gridDim.x * 256)
        m = fmaxf(m, s[i]);
    sm[threadIdx.x] = m; __syncthreads();
    for (int o = 128; o > 0; o >>= 1) {
        if (threadIdx.x < o) sm[threadIdx.x] = fmaxf(sm[threadIdx.x], sm[threadIdx.x + o]);
        __syncthreads();
    }
    if (!threadIdx.x) part[blockIdx.x] = sm[0];
}

__global__ void rmax_final(const float* __restrict__ part, int nb, float* __restrict__ out)
{
    __shared__ float sm[256];
    sm[threadIdx.x] = (threadIdx.x < nb) ? part[threadIdx.x] : -3.4e38f;
    __syncthreads();
    for (int o = 128; o > 0; o >>= 1) {
        if (threadIdx.x < o) sm[threadIdx.x] = fmaxf(sm[threadIdx.x], sm[threadIdx.x + o]);
        __syncthreads();
    }
    if (!threadIdx.x) out[0] = sm[0];
}

__global__ void exp_part(float* __restrict__ s, const float* __restrict__ mx, int n,
                         float* __restrict__ part)
{
    __shared__ float sm[256];
    float m = mx[0];
    float acc = 0.f;
    for (int i = blockIdx.x * 256 + threadIdx.x; i < n; i += gridDim.x * 256) {
        float e = expf(s[i] - m);
        s[i] = e;
        acc += e;
    }
    sm[threadIdx.x] = acc; __syncthreads();
    for (int o = 128; o > 0; o >>= 1) {
        if (threadIdx.x < o) sm[threadIdx.x] += sm[threadIdx.x + o];
        __syncthreads();
    }
    if (!threadIdx.x) part[blockIdx.x] = sm[0];
}

__global__ void rsum_final(const float* __restrict__ part, int nb, float* __restrict__ out)
{
    __shared__ float sm[256];
    sm[threadIdx.x] = (threadIdx.x < nb) ? part[threadIdx.x] : 0.f;
    __syncthreads();
    for (int o = 128; o > 0; o >>= 1) {
        if (threadIdx.x < o) sm[threadIdx.x] += sm[threadIdx.x + o];
        __syncthreads();
    }
    if (!threadIdx.x) out[0] = sm[0];
}

// out[c] += sum_r w[r]*v[r,c] / sum   (partial over row chunk blockIdx.y)
__global__ void attnv_kernel(const float* __restrict__ v, const float* __restrict__ w,
                             const float* __restrict__ sum, float* __restrict__ out, int n)
{
    int c = blockIdx.x * 256 + threadIdx.x;
    int chunk = (n + gridDim.y - 1) / gridDim.y;
    int r0 = blockIdx.y * chunk;
    int r1 = min(r0 + chunk, n);
    float acc = 0.f;
    for (int r = r0; r < r1; r++) acc += w[r] * v[(long)r * H + c];
    atomicAdd(&out[c], acc / sum[0]);
}

__global__ void scatter_win_kernel(const int* __restrict__ src, const int* __restrict__ dst,
                                   const int* __restrict__ ij, const float* __restrict__ hw,
                                   const float* __restrict__ he, float* __restrict__ agg)
{
    long idx = (long)blockIdx.x * blockDim.x + threadIdx.x;
    if (idx >= (long)ER * H) return;
    int e = (int)(idx >> 9), c = (int)(idx & 511);
    atomicAdd(&agg[((long)dst[e] << 9) + c],
              hw[((long)src[e] << 9) + c] + he[((long)ij[e] << 9) + c]);
}

__global__ void scatter_edge_kernel(const int* __restrict__ src, const int* __restrict__ dst,
                                    const float* __restrict__ he, float* __restrict__ agg)
{
    long idx = (long)blockIdx.x * blockDim.x + threadIdx.x;
    if (idx >= (long)EE * H) return;
    int e = (int)(idx >> 9), c = (int)(idx & 511);
    atomicAdd(&agg[((long)dst[e] << 9) + c], he[((long)src[e] << 9) + c]);
}

__global__ void count_kernel(const int* __restrict__ dst, float* __restrict__ cnt, int n)
{
    int e = blockIdx.x * 256 + threadIdx.x;
    if (e < n) atomicAdd(&cnt[dst[e]], 1.f);
}

__global__ void divide_kernel(float* __restrict__ agg, const float* __restrict__ cnt, int nrows)
{
    long idx = (long)blockIdx.x * blockDim.x + threadIdx.x;
    if (idx >= (long)nrows * H) return;
    agg[idx] /= fmaxf(cnt[idx >> 9], 1.f);
}

// h_w = leaky((acc + gs + bs) / NREL), in place on acc
__global__ void win_update_kernel(float* __restrict__ acc, const float* __restrict__ gs,
                                  const float* __restrict__ bs)
{
    long idx = (long)blockIdx.x * blockDim.x + threadIdx.x;
    if (idx >= (long)NW * H) return;
    int c = (int)(idx & 511);
    float v = (acc[idx] + gs[c] + bs[c]) * (1.f / (float)NREL);
    acc[idx] = leakyf(v);
}

__global__ void matsum3_kernel(const float* __restrict__ a, const float* __restrict__ b,
                               const float* __restrict__ c, float* __restrict__ o, int n)
{
    int i = blockIdx.x * 256 + threadIdx.x;
    if (i < n) o[i] = a[i] + b[i] + c[i];
}

// ------------------------------- host orchestration -------------------------------
static void gemm(const float* A, const float* B, float* C, int M, int N, int K,
                 const float* bias, int beta, int leaky)
{
    dim3 grid((N + 63) / 64, (M + 63) / 64);
    gemm_kernel<<<grid, 256>>>(A, B, C, M, N, K, bias, beta, leaky);
}

extern "C" void kernel_launch(void* const* d_in, const int* in_sizes, int n_in,
                              void* d_out, int out_size)
{
    const float* x_win       = (const float*)d_in[0];
    const float* x_edge      = (const float*)d_in[1];
    const float* W_pre_win   = (const float*)d_in[2];
    const float* W_post_win  = (const float*)d_in[3];
    const float* W_pre_edge  = (const float*)d_in[4];
    const float* W_post_edge = (const float*)d_in[5];
    const float* conv_Wl     = (const float*)d_in[6];
    const float* conv_Wr     = (const float*)d_in[7];
    const float* conv_Wg     = (const float*)d_in[8];
    const float* conv_b      = (const float*)d_in[9];
    const float* econv_Wl    = (const float*)d_in[10];
    const float* econv_Wr    = (const float*)d_in[11];
    const float* econv_b     = (const float*)d_in[12];
    const float* pool_lin1_W = (const float*)d_in[13];
    const float* pool_lin1_b = (const float*)d_in[14];
    const float* pool_S      = (const float*)d_in[15];
    const float* pool_Wq     = (const float*)d_in[16];
    const float* pool_Wk     = (const float*)d_in[17];
    const float* pool_Wv     = (const float*)d_in[18];
    const float* pool_lin2_W = (const float*)d_in[19];
    const float* pool_lin2_b = (const float*)d_in[20];
    const float* lin_W       = (const float*)d_in[21];
    const float* lin_b       = (const float*)d_in[22];
    const int* ein = (const int*)d_in[23];
    const int* eic = (const int*)d_in[24];
    const int* eis = (const int*)d_in[25];
    const int* ijn = (const int*)d_in[26];
    const int* ijc = (const int*)d_in[27];
    const int* ijs = (const int*)d_in[28];
    const int* eee = (const int*)d_in[29];

    float *hw, *hw2, *h1, *kbuf, *vbuf, *agg, *he, *he2, *agge, *cnt;
    float *sbuf, *part, *stat, *qv, *gv0, *gv, *gs, *bs, *Wsum, *Wgsum;
    cudaGetSymbolAddress((void**)&hw,    g_hw);
    cudaGetSymbolAddress((void**)&hw2,   g_hw2);
    cudaGetSymbolAddress((void**)&h1,    g_h1);
    cudaGetSymbolAddress((void**)&kbuf,  g_k);
    cudaGetSymbolAddress((void**)&vbuf,  g_v);
    cudaGetSymbolAddress((void**)&agg,   g_agg);
    cudaGetSymbolAddress((void**)&he,    g_he);
    cudaGetSymbolAddress((void**)&he2,   g_he2);
    cudaGetSymbolAddress((void**)&agge,  g_agge);
    cudaGetSymbolAddress((void**)&cnt,   g_cnt);
    cudaGetSymbolAddress((void**)&sbuf,  g_s);
    cudaGetSymbolAddress((void**)&part,  g_part);
    cudaGetSymbolAddress((void**)&stat,  g_stat);
    cudaGetSymbolAddress((void**)&qv,    g_q);
    cudaGetSymbolAddress((void**)&gv0,   g_gv0);
    cudaGetSymbolAddress((void**)&gv,    g_gv);
    cudaGetSymbolAddress((void**)&gs,    g_gs);
    cudaGetSymbolAddress((void**)&bs,    g_bs);
    cudaGetSymbolAddress((void**)&Wsum,  g_Wsum);
    cudaGetSymbolAddress((void**)&Wgsum, g_Wgsum);

    // ---- pretransforms ----
    gemm(x_win, W_pre_win, h1, NW, H, MDIM, nullptr, 0, 1);
    gemm(h1, W_post_win, hw, NW, H, H, nullptr, 0, 1);
    gemm(x_edge, W_pre_edge, agge, NE, H, ECH, nullptr, 0, 1);
    gemm(agge, W_post_edge, he, NE, H, H, nullptr, 0, 1);

    float* hwc = hw;  float* hwn = hw2;
    float* hec = he;  float* hen = he2;
    const float scale = 1.f / sqrtf((float)H);
    const int* srcs[NREL] = {ein, eic, eis};
    const int* ijx[NREL]  = {ijn, ijc, ijs};

    for (int l = 0; l < NLAYER; l++) {
        long wOff = (long)l * H * H;
        long wb   = (long)l * NREL * H * H;
        long bb   = (long)l * NREL * H;

        // ---- attention pooling ----
        gemm(hwc, pool_lin1_W + wOff, h1, NW, H, H, pool_lin1_b + l * H, 0, 0);
        vecmat_kernel<<<2, 256>>>(pool_S + l * H, pool_Wq + wOff, nullptr, qv, H, H);
        gemm(h1, pool_Wk + wOff, kbuf, NW, H, H, nullptr, 0, 0);
        gemm(h1, pool_Wv + wOff, vbuf, NW, H, H, nullptr, 0, 0);
        scores_kernel<<<(NW * 32 + 255) / 256, 256>>>(kbuf, qv, sbuf, NW, scale);
        rmax_part<<<240, 256>>>(sbuf, NW, part);
        rmax_final<<<1, 256>>>(part, 240, stat);
        exp_part<<<240, 256>>>(sbuf, stat, NW, part);
        rsum_final<<<1, 256>>>(part, 240, stat + 1);
        cudaMemsetAsync(gv0, 0, H * sizeof(float));
        {
            dim3 ag(H / 256, 79);
            attnv_kernel<<<ag, 256>>>(vbuf, sbuf, stat + 1, gv0, NW);
        }
        vecmat_kernel<<<2, 256>>>(gv0, pool_lin2_W + wOff, pool_lin2_b + l * H, gv, H, H);

        // ---- folded weight sums over relations ----
        matsum3_kernel<<<(H * H + 255) / 256, 256>>>(
            conv_Wg + wb, conv_Wg + wb + (long)H * H, conv_Wg + wb + 2L * H * H, Wgsum, H * H);
        vecmat_kernel<<<2, 256>>>(gv, Wgsum, nullptr, gs, H, H);
        matsum3_kernel<<<(H * H + 255) / 256, 256>>>(
            conv_Wr + wb, conv_Wr + wb + (long)H * H, conv_Wr + wb + 2L * H * H, Wsum, H * H);
        matsum3_kernel<<<(H + 255) / 256, 256>>>(
            conv_b + bb, conv_b + bb + H, conv_b + bb + 2 * H, bs, H);

        // ---- window conv: acc = h_w @ ΣWr + Σ_r agg_r @ Wl_r ----
        gemm(hwc, Wsum, hwn, NW, H, H, nullptr, 0, 0);
        for (int r = 0; r < NREL; r++) {
            cudaMemsetAsync(agg, 0, (size_t)NW * H * sizeof(float));
            cudaMemsetAsync(cnt, 0, NW * sizeof(float));
            scatter_win_kernel<<<(int)(((long)ER * H + 255) / 256), 256>>>(
                srcs[r], srcs[r] + ER, ijx[r], hwc, hec, agg);
            count_kernel<<<(ER + 255) / 256, 256>>>(srcs[r] + ER, cnt, ER);
            divide_kernel<<<(int)(((long)NW * H + 255) / 256), 256>>>(agg, cnt, NW);
            gemm(agg, conv_Wl + wb + (long)r * H * H, hwn, NW, H, H, nullptr, 1, 0);
        }
        win_update_kernel<<<(int)(((long)NW * H + 255) / 256), 256>>>(hwn, gs, bs);

        // ---- edge conv ----
        cudaMemsetAsync(agge, 0, (size_t)NE * H * sizeof(float));
        cudaMemsetAsync(cnt, 0, NE * sizeof(float));
        scatter_edge_kernel<<<(int)(((long)EE * H + 255) / 256), 256>>>(eee, eee + EE, hec, agge);
        count_kernel<<<(EE + 255) / 256, 256>>>(eee + EE, cnt, EE);
        divide_kernel<<<(int)(((long)NE * H + 255) / 256), 256>>>(agge, cnt, NE);
        gemm(agge, econv_Wl + wOff, hen, NE, H, H, nullptr, 0, 0);
        gemm(hec, econv_Wr + wOff, hen, NE, H, H, econv_b + l * H, 1, 1);

        // ---- rotate buffers ----
        float* t = hwc; hwc = hwn; hwn = t;
        t = hec; hec = hen; hen = t;
    }

    // ---- final linear ----
    gemm(hwc, lin_W, (float*)d_out, NW, OUT_DIM, H, lin_b, 0, 0);
}

// round 3
// speedup vs baseline: 4.0890x; 4.0890x over previous
#include <cuda_runtime.h>
#include <math.h>

#define NW 20000
#define NE 30000
#define ER 200000
#define EE 200000
#define H 512
#define MDIM 512
#define ECH 4101
#define OUT_DIM 250
#define NLAYER 4
#define NREL 3
#define SLOPE 0.2f

// ---------------- scratch (device globals; no runtime allocation) ----------------
__device__ float g_hw[NW * H];
__device__ float g_hw2[NW * H];
__device__ float g_h1[NW * H];
__device__ float g_k[NW * H];
__device__ float g_v[NW * H];
__device__ float g_agg[NW * H];
__device__ float g_he[NE * H];
__device__ float g_he2[NE * H];
__device__ float g_agge[NE * H];
__device__ float g_cnt[NE];
__device__ float g_s[NW];
__device__ float g_part[256];
__device__ float g_stat[2];
__device__ float g_q[H];
__device__ float g_gv0[H];
__device__ float g_gv[H];
__device__ float g_gs[H];
__device__ float g_bs[H];
__device__ float g_Wsum[H * H];
__device__ float g_Wgsum[H * H];

__device__ __forceinline__ float leakyf(float v) { return v > 0.f ? v : SLOPE * v; }

__device__ __forceinline__ unsigned f2tf32(float f) {
    unsigned r;
    asm("cvt.rna.tf32.f32 %0, %1;" : "=r"(r) : "f"(f));
    return r;
}

// =================== TF32 tensor-core GEMM ===================
// C[MxN] = A[MxK] @ B[KxN] (+C if beta) (+bias) (leaky)
// Block tile 128x128, K-tile 16, 8 warps each computing 64x32 via m16n8k8 tf32.
#define BM 128
#define BN 128
#define BKT 16
#define ASTRIDE 20   // BKT + 4 pad -> conflict-free A fragment LDS
#define BSTRIDE 132  // BN + 4 pad  -> 2-way max on B fragment LDS

__global__ __launch_bounds__(256, 2)
void mma_gemm_kernel(const float* __restrict__ A, const float* __restrict__ B,
                     float* __restrict__ C, int M, int N, int K,
                     const float* __restrict__ bias, int beta, int leaky)
{
    __shared__ unsigned As[2][BM][ASTRIDE];
    __shared__ unsigned Bs[2][BKT][BSTRIDE];

    const int tid  = threadIdx.x;
    const int lane = tid & 31;
    const int warp = tid >> 5;
    const int wm = warp & 1;        // 0..1  (64-row slabs)
    const int wn = warp >> 1;       // 0..3  (32-col slabs)
    const int grp = lane >> 2;      // 0..7
    const int tig = lane & 3;       // 0..3

    const int rowBase = blockIdx.y * BM;
    const int colBase = blockIdx.x * BN;

    const bool a4ok = ((K & 3) == 0);
    const bool b4ok = ((N & 3) == 0);

    float acc[4][4][4];
    #pragma unroll
    for (int i = 0; i < 4; i++)
        #pragma unroll
        for (int j = 0; j < 4; j++)
            #pragma unroll
            for (int q = 0; q < 4; q++) acc[i][j][q] = 0.f;

    const int ntiles = (K + BKT - 1) / BKT;

    // staging registers for one tile
    float aR[2][4], bR[2][4];

    // A tile: 128 rows x 16 cols -> 512 float4, 2 per thread
    // B tile: 16 rows x 128 cols -> 512 float4, 2 per thread
    auto loadRegs = [&](int t) {
        int k0 = t * BKT;
        #pragma unroll
        for (int i = 0; i < 2; i++) {
            int v = tid + i * 256;
            int r = v >> 2, c = (v & 3) * 4;
            int gr = rowBase + r, gc = k0 + c;
            float4 val = make_float4(0.f, 0.f, 0.f, 0.f);
            if (gr < M) {
                const float* p = A + (size_t)gr * K + gc;
                if (gc + 3 < K && a4ok) {
                    val = *(const float4*)p;
                } else {
                    if (gc + 0 < K) val.x = p[0];
                    if (gc + 1 < K) val.y = p[1];
                    if (gc + 2 < K) val.z = p[2];
                    if (gc + 3 < K) val.w = p[3];
                }
            }
            aR[i][0] = val.x; aR[i][1] = val.y; aR[i][2] = val.z; aR[i][3] = val.w;
        }
        #pragma unroll
        for (int i = 0; i < 2; i++) {
            int v = tid + i * 256;
            int r = v >> 5, c = (v & 31) * 4;
            int gr = k0 + r, gc = colBase + c;
            float4 val = make_float4(0.f, 0.f, 0.f, 0.f);
            if (gr < K) {
                const float* p = B + (size_t)gr * N + gc;
                if (gc + 3 < N && b4ok) {
                    val = *(const float4*)p;
                } else {
                    if (gc + 0 < N) val.x = p[0];
                    if (gc + 1 < N) val.y = p[1];
                    if (gc + 2 < N) val.z = p[2];
                    if (gc + 3 < N) val.w = p[3];
                }
            }
            bR[i][0] = val.x; bR[i][1] = val.y; bR[i][2] = val.z; bR[i][3] = val.w;
        }
    };

    auto stsTile = [&](int b) {
        #pragma unroll
        for (int i = 0; i < 2; i++) {
            int v = tid + i * 256;
            int r = v >> 2, c = (v & 3) * 4;
            #pragma unroll
            for (int q = 0; q < 4; q++) As[b][r][c + q] = f2tf32(aR[i][q]);
        }
        #pragma unroll
        for (int i = 0; i < 2; i++) {
            int v = tid + i * 256;
            int r = v >> 5, c = (v & 31) * 4;
            #pragma unroll
            for (int q = 0; q < 4; q++) Bs[b][r][c + q] = f2tf32(bR[i][q]);
        }
    };

    loadRegs(0);
    stsTile(0);

    for (int t = 0; t < ntiles; t++) {
        __syncthreads();
        if (t + 1 < ntiles) loadRegs(t + 1);
        int b = t & 1;
        #pragma unroll
        for (int kk = 0; kk < BKT; kk += 8) {
            unsigned bf[4][2];
            #pragma unroll
            for (int nt = 0; nt < 4; nt++) {
                int n = wn * 32 + nt * 8 + grp;
                bf[nt][0] = Bs[b][kk + tig][n];
                bf[nt][1] = Bs[b][kk + tig + 4][n];
            }
            #pragma unroll
            for (int mt = 0; mt < 4; mt++) {
                int r = wm * 64 + mt * 16 + grp;
                unsigned a0 = As[b][r][kk + tig];
                unsigned a1 = As[b][r + 8][kk + tig];
                unsigned a2 = As[b][r][kk + tig + 4];
                unsigned a3 = As[b][r + 8][kk + tig + 4];
                #pragma unroll
                for (int nt = 0; nt < 4; nt++) {
                    asm volatile(
                        "mma.sync.aligned.m16n8k8.row.col.f32.tf32.tf32.f32 "
                        "{%0,%1,%2,%3}, {%4,%5,%6,%7}, {%8,%9}, {%0,%1,%2,%3};\n"
                        : "+f"(acc[mt][nt][0]), "+f"(acc[mt][nt][1]),
                          "+f"(acc[mt][nt][2]), "+f"(acc[mt][nt][3])
                        : "r"(a0), "r"(a1), "r"(a2), "r"(a3),
                          "r"(bf[nt][0]), "r"(bf[nt][1]));
                }
            }
        }
        if (t + 1 < ntiles) stsTile((t + 1) & 1);
    }

    // epilogue
    #pragma unroll
    for (int mt = 0; mt < 4; mt++) {
        #pragma unroll
        for (int nt = 0; nt < 4; nt++) {
            int r0 = rowBase + wm * 64 + mt * 16 + grp;
            int c0 = colBase + wn * 32 + nt * 8 + tig * 2;
            #pragma unroll
            for (int half = 0; half < 2; half++) {
                int r = r0 + half * 8;
                if (r >= M) continue;
                #pragma unroll
                for (int j = 0; j < 2; j++) {
                    int c = c0 + j;
                    if (c >= N) continue;
                    float v = acc[mt][nt][half * 2 + j];
                    if (beta) v += C[(size_t)r * N + c];
                    if (bias) v += bias[c];
                    if (leaky) v = leakyf(v);
                    C[(size_t)r * N + c] = v;
                }
            }
        }
    }
}

// out[1,N] = x[1,K] @ W[K,N] (+bias)
__global__ void vecmat_kernel(const float* __restrict__ x, const float* __restrict__ W,
                              const float* __restrict__ bias, float* __restrict__ out,
                              int K, int N)
{
    int j = blockIdx.x * blockDim.x + threadIdx.x;
    if (j >= N) return;
    float acc = bias ? bias[j] : 0.f;
    for (int k = 0; k < K; k++) acc += x[k] * W[(size_t)k * N + j];
    out[j] = acc;
}

// s[i] = scale * dot(kmat[i,:], q)
__global__ void scores_kernel(const float* __restrict__ kmat, const float* __restrict__ q,
                              float* __restrict__ s, int n, float scale)
{
    int warp = (blockIdx.x * blockDim.x + threadIdx.x) >> 5;
    int lane = threadIdx.x & 31;
    if (warp >= n) return;
    const float* row = kmat + (size_t)warp * H;
    float acc = 0.f;
    for (int c = lane; c < H; c += 32) acc += row[c] * q[c];
    #pragma unroll
    for (int o = 16; o > 0; o >>= 1) acc += __shfl_down_sync(0xffffffffu, acc, o);
    if (!lane) s[warp] = acc * scale;
}

__global__ void rmax_part(const float* __restrict__ s, int n, float* __restrict__ part)
{
    __shared__ float sm[256];
    float m = -3.4e38f;
    for (int i = blockIdx.x * 256 + threadIdx.x; i < n; i += gridDim.x * 256)
        m = fmaxf(m, s[i]);
    sm[threadIdx.x] = m; __syncthreads();
    for (int o = 128; o > 0; o >>= 1) {
        if (threadIdx.x < o) sm[threadIdx.x] = fmaxf(sm[threadIdx.x], sm[threadIdx.x + o]);
        __syncthreads();
    }
    if (!threadIdx.x) part[blockIdx.x] = sm[0];
}

__global__ void rmax_final(const float* __restrict__ part, int nb, float* __restrict__ out)
{
    __shared__ float sm[256];
    sm[threadIdx.x] = (threadIdx.x < nb) ? part[threadIdx.x] : -3.4e38f;
    __syncthreads();
    for (int o = 128; o > 0; o >>= 1) {
        if (threadIdx.x < o) sm[threadIdx.x] = fmaxf(sm[threadIdx.x], sm[threadIdx.x + o]);
        __syncthreads();
    }
    if (!threadIdx.x) out[0] = sm[0];
}

__global__ void exp_part(float* __restrict__ s, const float* __restrict__ mx, int n,
                         float* __restrict__ part)
{
    __shared__ float sm[256];
    float m = mx[0];
    float acc = 0.f;
    for (int i = blockIdx.x * 256 + threadIdx.x; i < n; i += gridDim.x * 256) {
        float e = expf(s[i] - m);
        s[i] = e;
        acc += e;
    }
    sm[threadIdx.x] = acc; __syncthreads();
    for (int o = 128; o > 0; o >>= 1) {
        if (threadIdx.x < o) sm[threadIdx.x] += sm[threadIdx.x + o];
        __syncthreads();
    }
    if (!threadIdx.x) part[blockIdx.x] = sm[0];
}

__global__ void rsum_final(const float* __restrict__ part, int nb, float* __restrict__ out)
{
    __shared__ float sm[256];
    sm[threadIdx.x] = (threadIdx.x < nb) ? part[threadIdx.x] : 0.f;
    __syncthreads();
    for (int o = 128; o > 0; o >>= 1) {
        if (threadIdx.x < o) sm[threadIdx.x] += sm[threadIdx.x + o];
        __syncthreads();
    }
    if (!threadIdx.x) out[0] = sm[0];
}

// out[c] += sum_r w[r]*v[r,c] / sum   (partial over row chunk blockIdx.y)
__global__ void attnv_kernel(const float* __restrict__ v, const float* __restrict__ w,
                             const float* __restrict__ sum, float* __restrict__ out, int n)
{
    int c = blockIdx.x * 256 + threadIdx.x;
    int chunk = (n + gridDim.y - 1) / gridDim.y;
    int r0 = blockIdx.y * chunk;
    int r1 = min(r0 + chunk, n);
    float acc = 0.f;
    for (int r = r0; r < r1; r++) acc += w[r] * v[(size_t)r * H + c];
    atomicAdd(&out[c], acc / sum[0]);
}

// vectorized scatter: 4 channels per thread, red.global.add.v4.f32
__global__ void scatter_win_kernel(const int* __restrict__ src, const int* __restrict__ dst,
                                   const int* __restrict__ ij,
                                   const float4* __restrict__ hw,
                                   const float4* __restrict__ he, float* __restrict__ agg)
{
    long idx = (long)blockIdx.x * blockDim.x + threadIdx.x;
    if (idx >= (long)ER * (H / 4)) return;
    int e = (int)(idx >> 7), c = (int)(idx & 127);
    float4 a = hw[((long)src[e] << 7) + c];
    float4 b = he[((long)ij[e] << 7) + c];
    float* p = agg + ((long)dst[e] << 9) + (c << 2);
    asm volatile("red.global.add.v4.f32 [%0], {%1,%2,%3,%4};"
                 :: "l"(p), "f"(a.x + b.x), "f"(a.y + b.y),
                    "f"(a.z + b.z), "f"(a.w + b.w) : "memory");
}

__global__ void scatter_edge_kernel(const int* __restrict__ src, const int* __restrict__ dst,
                                    const float4* __restrict__ he, float* __restrict__ agg)
{
    long idx = (long)blockIdx.x * blockDim.x + threadIdx.x;
    if (idx >= (long)EE * (H / 4)) return;
    int e = (int)(idx >> 7), c = (int)(idx & 127);
    float4 a = he[((long)src[e] << 7) + c];
    float* p = agg + ((long)dst[e] << 9) + (c << 2);
    asm volatile("red.global.add.v4.f32 [%0], {%1,%2,%3,%4};"
                 :: "l"(p), "f"(a.x), "f"(a.y), "f"(a.z), "f"(a.w) : "memory");
}

__global__ void count_kernel(const int* __restrict__ dst, float* __restrict__ cnt, int n)
{
    int e = blockIdx.x * 256 + threadIdx.x;
    if (e < n) atomicAdd(&cnt[dst[e]], 1.f);
}

__global__ void divide_kernel(float* __restrict__ agg, const float* __restrict__ cnt, int nrows)
{
    long idx = (long)blockIdx.x * blockDim.x + threadIdx.x;
    if (idx >= (long)nrows * H) return;
    agg[idx] /= fmaxf(cnt[idx >> 9], 1.f);
}

// h_w = leaky((acc + gs + bs) / NREL), in place on acc
__global__ void win_update_kernel(float* __restrict__ acc, const float* __restrict__ gs,
                                  const float* __restrict__ bs)
{
    long idx = (long)blockIdx.x * blockDim.x + threadIdx.x;
    if (idx >= (long)NW * H) return;
    int c = (int)(idx & 511);
    float v = (acc[idx] + gs[c] + bs[c]) * (1.f / (float)NREL);
    acc[idx] = leakyf(v);
}

__global__ void matsum3_kernel(const float* __restrict__ a, const float* __restrict__ b,
                               const float* __restrict__ c, float* __restrict__ o, int n)
{
    int i = blockIdx.x * 256 + threadIdx.x;
    if (i < n) o[i] = a[i] + b[i] + c[i];
}

// ------------------------------- host orchestration -------------------------------
static void gemm(const float* A, const float* B, float* C, int M, int N, int K,
                 const float* bias, int beta, int leaky)
{
    dim3 grid((N + BN - 1) / BN, (M + BM - 1) / BM);
    mma_gemm_kernel<<<grid, 256>>>(A, B, C, M, N, K, bias, beta, leaky);
}

extern "C" void kernel_launch(void* const* d_in, const int* in_sizes, int n_in,
                              void* d_out, int out_size)
{
    const float* x_win       = (const float*)d_in[0];
    const float* x_edge      = (const float*)d_in[1];
    const float* W_pre_win   = (const float*)d_in[2];
    const float* W_post_win  = (const float*)d_in[3];
    const float* W_pre_edge  = (const float*)d_in[4];
    const float* W_post_edge = (const float*)d_in[5];
    const float* conv_Wl     = (const float*)d_in[6];
    const float* conv_Wr     = (const float*)d_in[7];
    const float* conv_Wg     = (const float*)d_in[8];
    const float* conv_b      = (const float*)d_in[9];
    const float* econv_Wl    = (const float*)d_in[10];
    const float* econv_Wr    = (const float*)d_in[11];
    const float* econv_b     = (const float*)d_in[12];
    const float* pool_lin1_W = (const float*)d_in[13];
    const float* pool_lin1_b = (const float*)d_in[14];
    const float* pool_S      = (const float*)d_in[15];
    const float* pool_Wq     = (const float*)d_in[16];
    const float* pool_Wk     = (const float*)d_in[17];
    const float* pool_Wv     = (const float*)d_in[18];
    const float* pool_lin2_W = (const float*)d_in[19];
    const float* pool_lin2_b = (const float*)d_in[20];
    const float* lin_W       = (const float*)d_in[21];
    const float* lin_b       = (const float*)d_in[22];
    const int* ein = (const int*)d_in[23];
    const int* eic = (const int*)d_in[24];
    const int* eis = (const int*)d_in[25];
    const int* ijn = (const int*)d_in[26];
    const int* ijc = (const int*)d_in[27];
    const int* ijs = (const int*)d_in[28];
    const int* eee = (const int*)d_in[29];

    float *hw, *hw2, *h1, *kbuf, *vbuf, *agg, *he, *he2, *agge, *cnt;
    float *sbuf, *part, *stat, *qv, *gv0, *gv, *gs, *bs, *Wsum, *Wgsum;
    cudaGetSymbolAddress((void**)&hw,    g_hw);
    cudaGetSymbolAddress((void**)&hw2,   g_hw2);
    cudaGetSymbolAddress((void**)&h1,    g_h1);
    cudaGetSymbolAddress((void**)&kbuf,  g_k);
    cudaGetSymbolAddress((void**)&vbuf,  g_v);
    cudaGetSymbolAddress((void**)&agg,   g_agg);
    cudaGetSymbolAddress((void**)&he,    g_he);
    cudaGetSymbolAddress((void**)&he2,   g_he2);
    cudaGetSymbolAddress((void**)&agge,  g_agge);
    cudaGetSymbolAddress((void**)&cnt,   g_cnt);
    cudaGetSymbolAddress((void**)&sbuf,  g_s);
    cudaGetSymbolAddress((void**)&part,  g_part);
    cudaGetSymbolAddress((void**)&stat,  g_stat);
    cudaGetSymbolAddress((void**)&qv,    g_q);
    cudaGetSymbolAddress((void**)&gv0,   g_gv0);
    cudaGetSymbolAddress((void**)&gv,    g_gv);
    cudaGetSymbolAddress((void**)&gs,    g_gs);
    cudaGetSymbolAddress((void**)&bs,    g_bs);
    cudaGetSymbolAddress((void**)&Wsum,  g_Wsum);
    cudaGetSymbolAddress((void**)&Wgsum, g_Wgsum);

    // ---- pretransforms ----
    gemm(x_win, W_pre_win, h1, NW, H, MDIM, nullptr, 0, 1);
    gemm(h1, W_post_win, hw, NW, H, H, nullptr, 0, 1);
    gemm(x_edge, W_pre_edge, agge, NE, H, ECH, nullptr, 0, 1);
    gemm(agge, W_post_edge, he, NE, H, H, nullptr, 0, 1);

    float* hwc = hw;  float* hwn = hw2;
    float* hec = he;  float* hen = he2;
    const float scale = 1.f / sqrtf((float)H);
    const int* srcs[NREL] = {ein, eic, eis};
    const int* ijx[NREL]  = {ijn, ijc, ijs};

    for (int l = 0; l < NLAYER; l++) {
        long wOff = (long)l * H * H;
        long wb   = (long)l * NREL * H * H;
        long bb   = (long)l * NREL * H;

        // ---- attention pooling ----
        gemm(hwc, pool_lin1_W + wOff, h1, NW, H, H, pool_lin1_b + l * H, 0, 0);
        vecmat_kernel<<<2, 256>>>(pool_S + l * H, pool_Wq + wOff, nullptr, qv, H, H);
        gemm(h1, pool_Wk + wOff, kbuf, NW, H, H, nullptr, 0, 0);
        gemm(h1, pool_Wv + wOff, vbuf, NW, H, H, nullptr, 0, 0);
        scores_kernel<<<(NW * 32 + 255) / 256, 256>>>(kbuf, qv, sbuf, NW, scale);
        rmax_part<<<240, 256>>>(sbuf, NW, part);
        rmax_final<<<1, 256>>>(part, 240, stat);
        exp_part<<<240, 256>>>(sbuf, stat, NW, part);
        rsum_final<<<1, 256>>>(part, 240, stat + 1);
        cudaMemsetAsync(gv0, 0, H * sizeof(float));
        {
            dim3 ag(H / 256, 79);
            attnv_kernel<<<ag, 256>>>(vbuf, sbuf, stat + 1, gv0, NW);
        }
        vecmat_kernel<<<2, 256>>>(gv0, pool_lin2_W + wOff, pool_lin2_b + l * H, gv, H, H);

        // ---- folded weight sums over relations ----
        matsum3_kernel<<<(H * H + 255) / 256, 256>>>(
            conv_Wg + wb, conv_Wg + wb + (long)H * H, conv_Wg + wb + 2L * H * H, Wgsum, H * H);
        vecmat_kernel<<<2, 256>>>(gv, Wgsum, nullptr, gs, H, H);
        matsum3_kernel<<<(H * H + 255) / 256, 256>>>(
            conv_Wr + wb, conv_Wr + wb + (long)H * H, conv_Wr + wb + 2L * H * H, Wsum, H * H);
        matsum3_kernel<<<(H + 255) / 256, 256>>>(
            conv_b + bb, conv_b + bb + H, conv_b + bb + 2 * H, bs, H);

        // ---- window conv: acc = h_w @ ΣWr + Σ_r agg_r @ Wl_r ----
        gemm(hwc, Wsum, hwn, NW, H, H, nullptr, 0, 0);
        for (int r = 0; r < NREL; r++) {
            cudaMemsetAsync(agg, 0, (size_t)NW * H * sizeof(float));
            cudaMemsetAsync(cnt, 0, NW * sizeof(float));
            scatter_win_kernel<<<(int)(((long)ER * (H / 4) + 255) / 256), 256>>>(
                srcs[r], srcs[r] + ER, ijx[r], (const float4*)hwc, (const float4*)hec, agg);
            count_kernel<<<(ER + 255) / 256, 256>>>(srcs[r] + ER, cnt, ER);
            divide_kernel<<<(int)(((long)NW * H + 255) / 256), 256>>>(agg, cnt, NW);
            gemm(agg, conv_Wl + wb + (long)r * H * H, hwn, NW, H, H, nullptr, 1, 0);
        }
        win_update_kernel<<<(int)(((long)NW * H + 255) / 256), 256>>>(hwn, gs, bs);

        // ---- edge conv ----
        cudaMemsetAsync(agge, 0, (size_t)NE * H * sizeof(float));
        cudaMemsetAsync(cnt, 0, NE * sizeof(float));
        scatter_edge_kernel<<<(int)(((long)EE * (H / 4) + 255) / 256), 256>>>(
            eee, eee + EE, (const float4*)hec, agge);
        count_kernel<<<(EE + 255) / 256, 256>>>(eee + EE, cnt, EE);
        divide_kernel<<<(int)(((long)NE * H + 255) / 256), 256>>>(agge, cnt, NE);
        gemm(agge, econv_Wl + wOff, hen, NE, H, H, nullptr, 0, 0);
        gemm(hec, econv_Wr + wOff, hen, NE, H, H, econv_b + l * H, 1, 1);

        // ---- rotate buffers ----
        float* t = hwc; hwc = hwn; hwn = t;
        t = hec; hec = hen; hen = t;
    }

    // ---- final linear ----
    gemm(hwc, lin_W, (float*)d_out, NW, OUT_DIM, H, lin_b, 0, 0);
}

// round 4
// speedup vs baseline: 5.6069x; 1.3712x over previous
#include <cuda_runtime.h>
#include <math.h>

#define NW 20000
#define NE 30000
#define ER 200000
#define EE 200000
#define H 512
#define MDIM 512
#define ECH 4101
#define ECHP 4104
#define OUT_DIM 250
#define NLAYER 4
#define NREL 3
#define SLOPE 0.2f

#define WCAT 2048   // [hw | agg0 | agg1 | agg2]
#define ECAT 1024   // [he | agge]

// ---------------- scratch (device globals; no runtime allocation) ----------------
__device__ float g_wcatA[(size_t)NW * WCAT];
__device__ float g_wcatB[(size_t)NW * WCAT];
__device__ float g_ecatA[(size_t)NE * ECAT];
__device__ float g_ecatB[(size_t)NE * ECAT];
__device__ float g_xpad[(size_t)NE * ECHP];
__device__ float g_wpad[(size_t)ECHP * H];
__device__ float g_tmp[(size_t)NE * H];
__device__ float g_Bw[(size_t)WCAT * H];
__device__ float g_Be[(size_t)ECAT * H];
__device__ float g_rw[NREL * NW];
__device__ float g_re[NE];
__device__ float g_s[NW];
__device__ float g_part[256];
__device__ float g_stat[2];
__device__ float g_vec[8 * H];      // q, wk, wfin, u, h1u, gv0, gvec, gs
__device__ float g_bs2[H];
__device__ float g_Wgsum[H * H];

__device__ __forceinline__ float leakyf(float v) { return v > 0.f ? v : SLOPE * v; }

// =================== TF32 tensor-core GEMM (cp.async, 3-stage) ===================
#define BM 128
#define BN 128
#define BKT 16
#define ASTRIDE 20
#define BSTRIDE 132
#define STAGES 3
#define GEMM_SMEM ((STAGES * BM * ASTRIDE + STAGES * BKT * BSTRIDE) * 4)

__device__ __forceinline__ void cp16(unsigned dst, const float* src, int sz) {
    asm volatile("cp.async.ca.shared.global [%0], [%1], 16, %2;\n"
                 :: "r"(dst), "l"(src), "r"(sz));
}

__global__ __launch_bounds__(256, 2)
void mma_gemm_async(const float* __restrict__ A, const float* __restrict__ B,
                    float* __restrict__ C, int M, int N, int K, int lda, int ldc,
                    const float* __restrict__ bias, float scale_ep, int leaky)
{
    extern __shared__ float smemBuf[];
    float (*As)[BM][ASTRIDE] = (float (*)[BM][ASTRIDE])smemBuf;
    float (*Bs)[BKT][BSTRIDE] = (float (*)[BKT][BSTRIDE])(smemBuf + STAGES * BM * ASTRIDE);
    unsigned aBase = (unsigned)__cvta_generic_to_shared(smemBuf);
    unsigned bBase = aBase + STAGES * BM * ASTRIDE * 4;

    const int tid  = threadIdx.x;
    const int lane = tid & 31;
    const int warp = tid >> 5;
    const int wm = warp & 1;
    const int wn = warp >> 1;
    const int grp = lane >> 2;
    const int tig = lane & 3;

    const int rowBase = blockIdx.y * BM;
    const int colBase = blockIdx.x * BN;
    const int ntiles = (K + BKT - 1) / BKT;

    float acc[4][4][4];
    #pragma unroll
    for (int i = 0; i < 4; i++)
        #pragma unroll
        for (int j = 0; j < 4; j++)
            #pragma unroll
            for (int q = 0; q < 4; q++) acc[i][j][q] = 0.f;

    // per-thread load coords
    const int arL = tid >> 2, acL = (tid & 3) * 4;       // +256 -> second half rows
    const int brL = tid >> 5, bcL = (tid & 31) * 4;

    auto issue = [&](int stage, int t) {
        int k0 = t * BKT;
        #pragma unroll
        for (int i = 0; i < 2; i++) {
            int r = arL + i * 64;
            int gr = rowBase + r, gc = k0 + acL;
            unsigned dst = aBase + (unsigned)(stage * BM * ASTRIDE + r * ASTRIDE + acL) * 4;
            cp16(dst, A + (size_t)gr * lda + gc, (gr < M && gc < K) ? 16 : 0);
        }
        #pragma unroll
        for (int i = 0; i < 2; i++) {
            int r = brL + i * 8;
            int gr = k0 + r, gc = colBase + bcL;
            unsigned dst = bBase + (unsigned)(stage * BKT * BSTRIDE + r * BSTRIDE + bcL) * 4;
            cp16(dst, B + (size_t)gr * N + gc, (gr < K && gc < N) ? 16 : 0);
        }
    };

    #pragma unroll
    for (int s = 0; s < STAGES - 1; s++) {
        if (s < ntiles) issue(s, s);
        asm volatile("cp.async.commit_group;\n");
    }

    for (int t = 0; t < ntiles; t++) {
        asm volatile("cp.async.wait_group %0;\n" :: "n"(STAGES - 2));
        __syncthreads();
        int nt_ = t + STAGES - 1;
        if (nt_ < ntiles) issue(nt_ % STAGES, nt_);
        asm volatile("cp.async.commit_group;\n");
        int b = t % STAGES;
        #pragma unroll
        for (int kk = 0; kk < BKT; kk += 8) {
            unsigned bf[4][2];
            #pragma unroll
            for (int nt = 0; nt < 4; nt++) {
                int n = wn * 32 + nt * 8 + grp;
                bf[nt][0] = __float_as_uint(Bs[b][kk + tig][n]);
                bf[nt][1] = __float_as_uint(Bs[b][kk + tig + 4][n]);
            }
            #pragma unroll
            for (int mt = 0; mt < 4; mt++) {
                int r = wm * 64 + mt * 16 + grp;
                unsigned a0 = __float_as_uint(As[b][r][kk + tig]);
                unsigned a1 = __float_as_uint(As[b][r + 8][kk + tig]);
                unsigned a2 = __float_as_uint(As[b][r][kk + tig + 4]);
                unsigned a3 = __float_as_uint(As[b][r + 8][kk + tig + 4]);
                #pragma unroll
                for (int nt = 0; nt < 4; nt++) {
                    asm volatile(
                        "mma.sync.aligned.m16n8k8.row.col.f32.tf32.tf32.f32 "
                        "{%0,%1,%2,%3}, {%4,%5,%6,%7}, {%8,%9}, {%0,%1,%2,%3};\n"
                        : "+f"(acc[mt][nt][0]), "+f"(acc[mt][nt][1]),
                          "+f"(acc[mt][nt][2]), "+f"(acc[mt][nt][3])
                        : "r"(a0), "r"(a1), "r"(a2), "r"(a3),
                          "r"(bf[nt][0]), "r"(bf[nt][1]));
                }
            }
        }
    }

    #pragma unroll
    for (int mt = 0; mt < 4; mt++) {
        #pragma unroll
        for (int nt = 0; nt < 4; nt++) {
            int r0 = rowBase + wm * 64 + mt * 16 + grp;
            int c0 = colBase + wn * 32 + nt * 8 + tig * 2;
            #pragma unroll
            for (int half = 0; half < 2; half++) {
                int r = r0 + half * 8;
                if (r >= M) continue;
                #pragma unroll
                for (int j = 0; j < 2; j++) {
                    int c = c0 + j;
                    if (c >= N) continue;
                    float v = acc[mt][nt][half * 2 + j];
                    if (bias) v += bias[c];
                    v *= scale_ep;
                    if (leaky) v = leakyf(v);
                    C[(size_t)r * ldc + c] = v;
                }
            }
        }
    }
}

// generic fallback (unaligned N) — register staging + cvt-free
__global__ __launch_bounds__(256, 2)
void mma_gemm_gen(const float* __restrict__ A, const float* __restrict__ B,
                  float* __restrict__ C, int M, int N, int K, int lda, int ldc,
                  const float* __restrict__ bias, float scale_ep, int leaky)
{
    __shared__ float As[2][BM][ASTRIDE];
    __shared__ float Bs[2][BKT][BSTRIDE];
    const int tid = threadIdx.x, lane = tid & 31, warp = tid >> 5;
    const int wm = warp & 1, wn = warp >> 1, grp = lane >> 2, tig = lane & 3;
    const int rowBase = blockIdx.y * BM, colBase = blockIdx.x * BN;
    float acc[4][4][4];
    #pragma unroll
    for (int i = 0; i < 4; i++)
        #pragma unroll
        for (int j = 0; j < 4; j++)
            #pragma unroll
            for (int q = 0; q < 4; q++) acc[i][j][q] = 0.f;
    const int ntiles = (K + BKT - 1) / BKT;
    float aR[2][4], bR[2][4];
    auto loadRegs = [&](int t) {
        int k0 = t * BKT;
        #pragma unroll
        for (int i = 0; i < 2; i++) {
            int v = tid + i * 256;
            int r = v >> 2, c = (v & 3) * 4;
            int gr = rowBase + r, gc = k0 + c;
            #pragma unroll
            for (int q = 0; q < 4; q++)
                aR[i][q] = (gr < M && gc + q < K) ? A[(size_t)gr * lda + gc + q] : 0.f;
        }
        #pragma unroll
        for (int i = 0; i < 2; i++) {
            int v = tid + i * 256;
            int r = v >> 5, c = (v & 31) * 4;
            int gr = k0 + r, gc = colBase + c;
            #pragma unroll
            for (int q = 0; q < 4; q++)
                bR[i][q] = (gr < K && gc + q < N) ? B[(size_t)gr * N + gc + q] : 0.f;
        }
    };
    auto stsTile = [&](int b) {
        #pragma unroll
        for (int i = 0; i < 2; i++) {
            int v = tid + i * 256;
            int r = v >> 2, c = (v & 3) * 4;
            #pragma unroll
            for (int q = 0; q < 4; q++) As[b][r][c + q] = aR[i][q];
        }
        #pragma unroll
        for (int i = 0; i < 2; i++) {
            int v = tid + i * 256;
            int r = v >> 5, c = (v & 31) * 4;
            #pragma unroll
            for (int q = 0; q < 4; q++) Bs[b][r][c + q] = bR[i][q];
        }
    };
    loadRegs(0); stsTile(0);
    for (int t = 0; t < ntiles; t++) {
        __syncthreads();
        if (t + 1 < ntiles) loadRegs(t + 1);
        int b = t & 1;
        #pragma unroll
        for (int kk = 0; kk < BKT; kk += 8) {
            unsigned bf[4][2];
            #pragma unroll
            for (int nt = 0; nt < 4; nt++) {
                int n = wn * 32 + nt * 8 + grp;
                bf[nt][0] = __float_as_uint(Bs[b][kk + tig][n]);
                bf[nt][1] = __float_as_uint(Bs[b][kk + tig + 4][n]);
            }
            #pragma unroll
            for (int mt = 0; mt < 4; mt++) {
                int r = wm * 64 + mt * 16 + grp;
                unsigned a0 = __float_as_uint(As[b][r][kk + tig]);
                unsigned a1 = __float_as_uint(As[b][r + 8][kk + tig]);
                unsigned a2 = __float_as_uint(As[b][r][kk + tig + 4]);
                unsigned a3 = __float_as_uint(As[b][r + 8][kk + tig + 4]);
                #pragma unroll
                for (int nt = 0; nt < 4; nt++) {
                    asm volatile(
                        "mma.sync.aligned.m16n8k8.row.col.f32.tf32.tf32.f32 "
                        "{%0,%1,%2,%3}, {%4,%5,%6,%7}, {%8,%9}, {%0,%1,%2,%3};\n"
                        : "+f"(acc[mt][nt][0]), "+f"(acc[mt][nt][1]),
                          "+f"(acc[mt][nt][2]), "+f"(acc[mt][nt][3])
                        : "r"(a0), "r"(a1), "r"(a2), "r"(a3),
                          "r"(bf[nt][0]), "r"(bf[nt][1]));
                }
            }
        }
        if (t + 1 < ntiles) stsTile((t + 1) & 1);
    }
    #pragma unroll
    for (int mt = 0; mt < 4; mt++)
        #pragma unroll
        for (int nt = 0; nt < 4; nt++) {
            int r0 = rowBase + wm * 64 + mt * 16 + grp;
            int c0 = colBase + wn * 32 + nt * 8 + tig * 2;
            #pragma unroll
            for (int half = 0; half < 2; half++) {
                int r = r0 + half * 8;
                if (r >= M) continue;
                #pragma unroll
                for (int j = 0; j < 2; j++) {
                    int c = c0 + j;
                    if (c >= N) continue;
                    float v = acc[mt][nt][half * 2 + j];
                    if (bias) v += bias[c];
                    v *= scale_ep;
                    if (leaky) v = leakyf(v);
                    C[(size_t)r * ldc + c] = v;
                }
            }
        }
}

// ---------------------------- small kernels ----------------------------
__global__ void padx_kernel(const float* __restrict__ x, float* __restrict__ xp)
{
    size_t idx = (size_t)blockIdx.x * blockDim.x + threadIdx.x;
    if (idx >= (size_t)NE * ECHP) return;
    int r = (int)(idx / ECHP), c = (int)(idx % ECHP);
    xp[idx] = (c < ECH) ? x[(size_t)r * ECH + c] : 0.f;
}

__global__ void padw_kernel(const float* __restrict__ w, float* __restrict__ wp)
{
    size_t idx = (size_t)blockIdx.x * blockDim.x + threadIdx.x;
    if (idx >= (size_t)ECHP * H) return;
    int r = (int)(idx / H);
    wp[idx] = (r < ECH) ? w[idx - (size_t)0] : 0.f;  // same linear idx while r < ECH
}

__global__ void count_kernel(const int* __restrict__ dst, float* __restrict__ cnt, int n)
{
    int e = blockIdx.x * 256 + threadIdx.x;
    if (e < n) atomicAdd(&cnt[dst[e]], 1.f);
}

__global__ void recip_kernel(float* __restrict__ c, int n)
{
    int i = blockIdx.x * 256 + threadIdx.x;
    if (i < n) c[i] = 1.f / fmaxf(c[i], 1.f);
}

// out[c]=sum_j W[c,j]*v[j]  (warp per row)
__global__ void rowdot_kernel(const float* __restrict__ W, const float* __restrict__ v,
                              float* __restrict__ out)
{
    int row = (blockIdx.x * blockDim.x + threadIdx.x) >> 5;
    int lane = threadIdx.x & 31;
    if (row >= H) return;
    const float* p = W + (size_t)row * H;
    float acc = 0.f;
    for (int j = lane; j < H; j += 32) acc += p[j] * v[j];
    #pragma unroll
    for (int o = 16; o > 0; o >>= 1) acc += __shfl_down_sync(0xffffffffu, acc, o);
    if (!lane) out[row] = acc;
}

// out[j]=sum_k x[k]*W[k,j] (+bias)
__global__ void vecmat_kernel(const float* __restrict__ x, const float* __restrict__ W,
                              const float* __restrict__ bias, float* __restrict__ out)
{
    int j = blockIdx.x * blockDim.x + threadIdx.x;
    if (j >= H) return;
    float acc = bias ? bias[j] : 0.f;
    for (int k = 0; k < H; k++) acc += x[k] * W[(size_t)k * H + j];
    out[j] = acc;
}

__global__ void scores_kernel(const float* __restrict__ hw, int lda,
                              const float* __restrict__ w, float* __restrict__ s,
                              float scale)
{
    int row = (blockIdx.x * blockDim.x + threadIdx.x) >> 5;
    int lane = threadIdx.x & 31;
    if (row >= NW) return;
    const float* p = hw + (size_t)row * lda;
    float acc = 0.f;
    for (int c = lane; c < H; c += 32) acc += p[c] * w[c];
    #pragma unroll
    for (int o = 16; o > 0; o >>= 1) acc += __shfl_down_sync(0xffffffffu, acc, o);
    if (!lane) s[row] = acc * scale;
}

__global__ void rmax_part(const float* __restrict__ s, int n, float* __restrict__ part)
{
    __shared__ float sm[256];
    float m = -3.4e38f;
    for (int i = blockIdx.x * 256 + threadIdx.x; i < n; i += gridDim.x * 256)
        m = fmaxf(m, s[i]);
    sm[threadIdx.x] = m; __syncthreads();
    for (int o = 128; o > 0; o >>= 1) {
        if (threadIdx.x < o) sm[threadIdx.x] = fmaxf(sm[threadIdx.x], sm[threadIdx.x + o]);
        __syncthreads();
    }
    if (!threadIdx.x) part[blockIdx.x] = sm[0];
}

__global__ void rmax_final(const float* __restrict__ part, int nb, float* __restrict__ out)
{
    __shared__ float sm[256];
    sm[threadIdx.x] = (threadIdx.x < nb) ? part[threadIdx.x] : -3.4e38f;
    __syncthreads();
    for (int o = 128; o > 0; o >>= 1) {
        if (threadIdx.x < o) sm[threadIdx.x] = fmaxf(sm[threadIdx.x], sm[threadIdx.x + o]);
        __syncthreads();
    }
    if (!threadIdx.x) out[0] = sm[0];
}

__global__ void exp_part(float* __restrict__ s, const float* __restrict__ mx, int n,
                         float* __restrict__ part)
{
    __shared__ float sm[256];
    float m = mx[0];
    float acc = 0.f;
    for (int i = blockIdx.x * 256 + threadIdx.x; i < n; i += gridDim.x * 256) {
        float e = expf(s[i] - m);
        s[i] = e;
        acc += e;
    }
    sm[threadIdx.x] = acc; __syncthreads();
    for (int o = 128; o > 0; o >>= 1) {
        if (threadIdx.x < o) sm[threadIdx.x] += sm[threadIdx.x + o];
        __syncthreads();
    }
    if (!threadIdx.x) part[blockIdx.x] = sm[0];
}

__global__ void rsum_final(const float* __restrict__ part, int nb, float* __restrict__ out)
{
    __shared__ float sm[256];
    sm[threadIdx.x] = (threadIdx.x < nb) ? part[threadIdx.x] : 0.f;
    __syncthreads();
    for (int o = 128; o > 0; o >>= 1) {
        if (threadIdx.x < o) sm[threadIdx.x] += sm[threadIdx.x + o];
        __syncthreads();
    }
    if (!threadIdx.x) out[0] = sm[0];
}

// u[c] += sum_r w[r]*hw[r,c]/sum
__global__ void attnv_kernel(const float* __restrict__ hw, int lda,
                             const float* __restrict__ w, const float* __restrict__ sum,
                             float* __restrict__ out, int n)
{
    int c = blockIdx.x * 256 + threadIdx.x;
    int chunk = (n + gridDim.y - 1) / gridDim.y;
    int r0 = blockIdx.y * chunk;
    int r1 = min(r0 + chunk, n);
    float acc = 0.f;
    for (int r = r0; r < r1; r++) acc += w[r] * hw[(size_t)r * lda + c];
    atomicAdd(&out[c], acc / sum[0]);
}

// build Bw: rows[0,512)=sum_r Wr, rows[512+512r+k]=Wl_r[k]
__global__ void build_bw_kernel(const float* __restrict__ Wl, const float* __restrict__ Wr,
                                float* __restrict__ out)
{
    size_t idx = (size_t)blockIdx.x * blockDim.x + threadIdx.x;
    if (idx >= (size_t)WCAT * H) return;
    int row = (int)(idx / H), j = (int)(idx % H);
    if (row < H) {
        out[idx] = Wr[(size_t)row * H + j] + Wr[(size_t)(H + row) * H + j]
                 + Wr[(size_t)(2 * H + row) * H + j];
    } else {
        out[idx] = Wl[(size_t)(row - H) * H + j];
    }
}

// build Be: rows[0,512)=Wr, rows[512,1024)=Wl
__global__ void build_be_kernel(const float* __restrict__ Wl, const float* __restrict__ Wr,
                                float* __restrict__ out)
{
    size_t idx = (size_t)blockIdx.x * blockDim.x + threadIdx.x;
    if (idx >= (size_t)ECAT * H) return;
    int row = (int)(idx / H), j = (int)(idx % H);
    out[idx] = (row < H) ? Wr[(size_t)row * H + j] : Wl[(size_t)(row - H) * H + j];
}

__global__ void matsum3_kernel(const float* __restrict__ a, const float* __restrict__ b,
                               const float* __restrict__ c, float* __restrict__ o, int n)
{
    int i = blockIdx.x * 256 + threadIdx.x;
    if (i < n) o[i] = a[i] + b[i] + c[i];
}

// bs2 = gs + b0 + b1 + b2
__global__ void bs2_kernel(const float* __restrict__ gs, const float* __restrict__ b,
                           float* __restrict__ out)
{
    int i = blockIdx.x * 256 + threadIdx.x;
    if (i < H) out[i] = gs[i] + b[i] + b[H + i] + b[2 * H + i];
}

// zero a strided float4 region
__global__ void zero_region(float4* __restrict__ base, int rows, int ldF4,
                            int startF4, int nF4)
{
    size_t idx = (size_t)blockIdx.x * blockDim.x + threadIdx.x;
    if (idx >= (size_t)rows * nF4) return;
    int r = (int)(idx / nF4), c = (int)(idx % nF4);
    base[(size_t)r * ldF4 + startF4 + c] = make_float4(0.f, 0.f, 0.f, 0.f);
}

// scatter (window): agg[dst] += (hw[src]+he[ij]) * recip[dst], strided layouts
__global__ void scatter_win_kernel(const int* __restrict__ src, const int* __restrict__ dst,
                                   const int* __restrict__ ij,
                                   const float4* __restrict__ wcat,
                                   const float4* __restrict__ ecat,
                                   float* __restrict__ aggOut,  // wcat + aggOffset (floats)
                                   const float* __restrict__ recip)
{
    size_t idx = (size_t)blockIdx.x * blockDim.x + threadIdx.x;
    if (idx >= (size_t)ER * (H / 4)) return;
    int e = (int)(idx >> 7), c = (int)(idx & 127);
    int d = dst[e];
    float rc = recip[d];
    float4 a = wcat[(size_t)src[e] * (WCAT / 4) + c];
    float4 b = ecat[(size_t)ij[e] * (ECAT / 4) + c];
    float* p = aggOut + (size_t)d * WCAT + (c << 2);
    asm volatile("red.global.add.v4.f32 [%0], {%1,%2,%3,%4};"
                 :: "l"(p), "f"((a.x + b.x) * rc), "f"((a.y + b.y) * rc),
                    "f"((a.z + b.z) * rc), "f"((a.w + b.w) * rc) : "memory");
}

__global__ void scatter_edge_kernel(const int* __restrict__ src, const int* __restrict__ dst,
                                    const float4* __restrict__ ecat,
                                    float* __restrict__ aggOut,
                                    const float* __restrict__ recip)
{
    size_t idx = (size_t)blockIdx.x * blockDim.x + threadIdx.x;
    if (idx >= (size_t)EE * (H / 4)) return;
    int e = (int)(idx >> 7), c = (int)(idx & 127);
    int d = dst[e];
    float rc = recip[d];
    float4 a = ecat[(size_t)src[e] * (ECAT / 4) + c];
    float* p = aggOut + (size_t)d * ECAT + (c << 2);
    asm volatile("red.global.add.v4.f32 [%0], {%1,%2,%3,%4};"
                 :: "l"(p), "f"(a.x * rc), "f"(a.y * rc), "f"(a.z * rc), "f"(a.w * rc)
                 : "memory");
}

// ------------------------------- host orchestration -------------------------------
static void gemmA(const float* A, const float* B, float* C, int M, int N, int K,
                  int lda, int ldc, const float* bias, float scale, int leaky)
{
    dim3 grid((N + BN - 1) / BN, (M + BM - 1) / BM);
    mma_gemm_async<<<grid, 256, GEMM_SMEM>>>(A, B, C, M, N, K, lda, ldc, bias, scale, leaky);
}

static void gemmG(const float* A, const float* B, float* C, int M, int N, int K,
                  int lda, int ldc, const float* bias, float scale, int leaky)
{
    dim3 grid((N + BN - 1) / BN, (M + BM - 1) / BM);
    mma_gemm_gen<<<grid, 256>>>(A, B, C, M, N, K, lda, ldc, bias, scale, leaky);
}

extern "C" void kernel_launch(void* const* d_in, const int* in_sizes, int n_in,
                              void* d_out, int out_size)
{
    const float* x_win       = (const float*)d_in[0];
    const float* x_edge      = (const float*)d_in[1];
    const float* W_pre_win   = (const float*)d_in[2];
    const float* W_post_win  = (const float*)d_in[3];
    const float* W_pre_edge  = (const float*)d_in[4];
    const float* W_post_edge = (const float*)d_in[5];
    const float* conv_Wl     = (const float*)d_in[6];
    const float* conv_Wr     = (const float*)d_in[7];
    const float* conv_Wg     = (const float*)d_in[8];
    const float* conv_b      = (const float*)d_in[9];
    const float* econv_Wl    = (const float*)d_in[10];
    const float* econv_Wr    = (const float*)d_in[11];
    const float* econv_b     = (const float*)d_in[12];
    const float* pool_lin1_W = (const float*)d_in[13];
    const float* pool_lin1_b = (const float*)d_in[14];
    const float* pool_S      = (const float*)d_in[15];
    const float* pool_Wq     = (const float*)d_in[16];
    const float* pool_Wk     = (const float*)d_in[17];
    const float* pool_Wv     = (const float*)d_in[18];
    const float* pool_lin2_W = (const float*)d_in[19];
    const float* pool_lin2_b = (const float*)d_in[20];
    const float* lin_W       = (const float*)d_in[21];
    const float* lin_b       = (const float*)d_in[22];
    const int* ein = (const int*)d_in[23];
    const int* eic = (const int*)d_in[24];
    const int* eis = (const int*)d_in[25];
    const int* ijn = (const int*)d_in[26];
    const int* ijc = (const int*)d_in[27];
    const int* ijs = (const int*)d_in[28];
    const int* eee = (const int*)d_in[29];

    static int smemSet = 0;
    if (!smemSet) {
        cudaFuncSetAttribute(mma_gemm_async, cudaFuncAttributeMaxDynamicSharedMemorySize,
                             GEMM_SMEM);
        smemSet = 1;
    }

    float *wcatA, *wcatB, *ecatA, *ecatB, *xpad, *wpad, *tmp, *Bw, *Be;
    float *rw, *re, *sbuf, *part, *stat, *vec, *bs2, *Wgsum;
    cudaGetSymbolAddress((void**)&wcatA, g_wcatA);
    cudaGetSymbolAddress((void**)&wcatB, g_wcatB);
    cudaGetSymbolAddress((void**)&ecatA, g_ecatA);
    cudaGetSymbolAddress((void**)&ecatB, g_ecatB);
    cudaGetSymbolAddress((void**)&xpad,  g_xpad);
    cudaGetSymbolAddress((void**)&wpad,  g_wpad);
    cudaGetSymbolAddress((void**)&tmp,   g_tmp);
    cudaGetSymbolAddress((void**)&Bw,    g_Bw);
    cudaGetSymbolAddress((void**)&Be,    g_Be);
    cudaGetSymbolAddress((void**)&rw,    g_rw);
    cudaGetSymbolAddress((void**)&re,    g_re);
    cudaGetSymbolAddress((void**)&sbuf,  g_s);
    cudaGetSymbolAddress((void**)&part,  g_part);
    cudaGetSymbolAddress((void**)&stat,  g_stat);
    cudaGetSymbolAddress((void**)&vec,   g_vec);
    cudaGetSymbolAddress((void**)&bs2,   g_bs2);
    cudaGetSymbolAddress((void**)&Wgsum, g_Wgsum);

    float* qv   = vec;
    float* wk   = vec + H;
    float* wfin = vec + 2 * H;
    float* u    = vec + 3 * H;
    float* h1u  = vec + 4 * H;
    float* gv0  = vec + 5 * H;
    float* gvec = vec + 6 * H;
    float* gs   = vec + 7 * H;

    // ---- one-time (per launch) precompute ----
    padx_kernel<<<(int)(((size_t)NE * ECHP + 255) / 256), 256>>>(x_edge, xpad);
    padw_kernel<<<(int)(((size_t)ECHP * H + 255) / 256), 256>>>(W_pre_edge, wpad);
    const int* srcs[NREL] = {ein, eic, eis};
    const int* ijx[NREL]  = {ijn, ijc, ijs};
    cudaMemsetAsync(rw, 0, NREL * NW * sizeof(float));
    cudaMemsetAsync(re, 0, NE * sizeof(float));
    for (int r = 0; r < NREL; r++) {
        count_kernel<<<(ER + 255) / 256, 256>>>(srcs[r] + ER, rw + r * NW, ER);
        recip_kernel<<<(NW + 255) / 256, 256>>>(rw + r * NW, NW);
    }
    count_kernel<<<(EE + 255) / 256, 256>>>(eee + EE, re, EE);
    recip_kernel<<<(NE + 255) / 256, 256>>>(re, NE);

    // ---- pretransforms ----
    gemmA(x_win, W_pre_win, tmp, NW, H, MDIM, MDIM, H, nullptr, 1.f, 1);
    gemmA(tmp, W_post_win, wcatA, NW, H, H, H, WCAT, nullptr, 1.f, 1);
    gemmA(xpad, wpad, tmp, NE, H, ECHP, ECHP, H, nullptr, 1.f, 1);
    gemmA(tmp, W_post_edge, ecatA, NE, H, H, H, ECAT, nullptr, 1.f, 1);

    float* wA = wcatA; float* wB = wcatB;
    float* eA = ecatA; float* eB = ecatB;
    const float scale = 1.f / sqrtf((float)H);

    for (int l = 0; l < NLAYER; l++) {
        size_t wOff = (size_t)l * H * H;
        size_t wb   = (size_t)l * NREL * H * H;
        size_t bb   = (size_t)l * NREL * H;

        // ---- pooling (algebraically reduced) ----
        vecmat_kernel<<<2, 256>>>(pool_S + (size_t)l * H, pool_Wq + wOff, nullptr, qv);
        rowdot_kernel<<<64, 256>>>(pool_Wk + wOff, qv, wk);
        rowdot_kernel<<<64, 256>>>(pool_lin1_W + wOff, wk, wfin);
        scores_kernel<<<(NW * 32 + 255) / 256, 256>>>(wA, WCAT, wfin, sbuf, scale);
        rmax_part<<<240, 256>>>(sbuf, NW, part);
        rmax_final<<<1, 256>>>(part, 240, stat);
        exp_part<<<240, 256>>>(sbuf, stat, NW, part);
        rsum_final<<<1, 256>>>(part, 240, stat + 1);
        cudaMemsetAsync(u, 0, H * sizeof(float));
        {
            dim3 ag(H / 256, 79);
            attnv_kernel<<<ag, 256>>>(wA, WCAT, sbuf, stat + 1, u, NW);
        }
        vecmat_kernel<<<2, 256>>>(u, pool_lin1_W + wOff, pool_lin1_b + (size_t)l * H, h1u);
        vecmat_kernel<<<2, 256>>>(h1u, pool_Wv + wOff, nullptr, gv0);
        vecmat_kernel<<<2, 256>>>(gv0, pool_lin2_W + wOff, pool_lin2_b + (size_t)l * H, gvec);
        matsum3_kernel<<<(H * H + 255) / 256, 256>>>(
            conv_Wg + wb, conv_Wg + wb + (size_t)H * H, conv_Wg + wb + 2 * (size_t)H * H,
            Wgsum, H * H);
        vecmat_kernel<<<2, 256>>>(gvec, Wgsum, nullptr, gs);
        bs2_kernel<<<2, 256>>>(gs, conv_b + bb, bs2);

        // ---- weights concat ----
        build_bw_kernel<<<(int)(((size_t)WCAT * H + 255) / 256), 256>>>(
            conv_Wl + wb, conv_Wr + wb, Bw);
        build_be_kernel<<<(int)(((size_t)ECAT * H + 255) / 256), 256>>>(
            econv_Wl + wOff, econv_Wr + wOff, Be);

        // ---- scatters (mean folded in) ----
        zero_region<<<(int)(((size_t)NW * 384 + 255) / 256), 256>>>(
            (float4*)wA, NW, WCAT / 4, H / 4, 3 * H / 4);
        zero_region<<<(int)(((size_t)NE * 128 + 255) / 256), 256>>>(
            (float4*)eA, NE, ECAT / 4, H / 4, H / 4);
        for (int r = 0; r < NREL; r++) {
            scatter_win_kernel<<<(int)(((size_t)ER * (H / 4) + 255) / 256), 256>>>(
                srcs[r], srcs[r] + ER, ijx[r], (const float4*)wA, (const float4*)eA,
                wA + (size_t)(1 + r) * H, rw + r * NW);
        }
        scatter_edge_kernel<<<(int)(((size_t)EE * (H / 4) + 255) / 256), 256>>>(
            eee, eee + EE, (const float4*)eA, eA + H, re);

        // ---- fused conv GEMMs ----
        gemmA(wA, Bw, wB, NW, H, WCAT, WCAT, WCAT, bs2, 1.f / (float)NREL, 1);
        gemmA(eA, Be, eB, NE, H, ECAT, ECAT, ECAT, econv_b + (size_t)l * H, 1.f, 1);

        float* t = wA; wA = wB; wB = t;
        t = eA; eA = eB; eB = t;
    }

    // ---- final linear (N=250 unaligned -> generic) ----
    gemmG(wA, lin_W, (float*)d_out, NW, OUT_DIM, H, WCAT, OUT_DIM, lin_b, 1.f, 0);
}

// round 5
// speedup vs baseline: 7.2666x; 1.2960x over previous
#include <cuda_runtime.h>
#include <math.h>

#define NW 20000
#define NE 30000
#define ER 200000
#define EE 200000
#define H 512
#define MDIM 512
#define ECH 4101
#define ECHP 4104
#define OUT_DIM 250
#define NLAYER 4
#define NREL 3
#define SLOPE 0.2f

#define WCAT 2048   // [hw | agg0 | agg1 | agg2]
#define ECAT 1024   // [he | agge]

// ---------------- scratch (device globals; no runtime allocation) ----------------
__device__ float g_wcatA[(size_t)NW * WCAT];
__device__ float g_wcatB[(size_t)NW * WCAT];
__device__ float g_ecatA[(size_t)NE * ECAT];
__device__ float g_ecatB[(size_t)NE * ECAT];
__device__ float g_xpad[(size_t)NE * ECHP];
__device__ float g_wpad[(size_t)ECHP * H];
__device__ float g_tmp[(size_t)NE * H];
__device__ float g_Bw[(size_t)WCAT * H];
__device__ float g_Be[(size_t)ECAT * H];
__device__ float g_s[NW];
__device__ float g_part[256];
__device__ float g_stat[2];
__device__ float g_vec[8 * H];
__device__ float g_bs2[H];
__device__ float g_Wgsum[H * H];
// CSR structures
__device__ int g_cnti[NE];
__device__ int g_cur[NE];
__device__ int g_offw[NREL * (NW + 1)];
__device__ int g_offe[NE + 1];
__device__ int g_psrcw[NREL * ER];
__device__ int g_pijw[NREL * ER];
__device__ int g_psrce[EE];

__device__ __forceinline__ float leakyf(float v) { return v > 0.f ? v : SLOPE * v; }

__device__ __forceinline__ float rna(float f) {
    unsigned u;
    asm("cvt.rna.tf32.f32 %0, %1;" : "=r"(u) : "f"(f));
    return __uint_as_float(u);
}

// =================== TF32 tensor-core GEMM (cp.async, 2-stage, BKT=32) ===========
#define BM 128
#define BN 128
#define BKT 32
#define ASTRIDE 36
#define BSTRIDE 132
#define STAGES 2
#define GEMM_SMEM ((STAGES * BM * ASTRIDE + STAGES * BKT * BSTRIDE) * 4)

__device__ __forceinline__ void cp16(unsigned dst, const float* src, int sz) {
    asm volatile("cp.async.ca.shared.global [%0], [%1], 16, %2;\n"
                 :: "r"(dst), "l"(src), "r"(sz));
}

__global__ __launch_bounds__(256, 2)
void mma_gemm_async(const float* __restrict__ A, const float* __restrict__ B,
                    float* __restrict__ C, int M, int N, int K, int lda, int ldc,
                    const float* __restrict__ bias, float scale_ep, int leaky, int rnd)
{
    extern __shared__ float smemBuf[];
    float (*As)[BM][ASTRIDE] = (float (*)[BM][ASTRIDE])smemBuf;
    float (*Bs)[BKT][BSTRIDE] = (float (*)[BKT][BSTRIDE])(smemBuf + STAGES * BM * ASTRIDE);
    unsigned aBase = (unsigned)__cvta_generic_to_shared(smemBuf);
    unsigned bBase = aBase + STAGES * BM * ASTRIDE * 4;

    const int tid  = threadIdx.x;
    const int lane = tid & 31;
    const int warp = tid >> 5;
    const int wm = warp & 1;
    const int wn = warp >> 1;
    const int grp = lane >> 2;
    const int tig = lane & 3;

    const int rowBase = blockIdx.y * BM;
    const int colBase = blockIdx.x * BN;
    const int ntiles = (K + BKT - 1) / BKT;

    float acc[4][4][4];
    #pragma unroll
    for (int i = 0; i < 4; i++)
        #pragma unroll
        for (int j = 0; j < 4; j++)
            #pragma unroll
            for (int q = 0; q < 4; q++) acc[i][j][q] = 0.f;

    // A tile: 128x32 = 1024 f4, 4/thread ; B tile: 32x128 = 1024 f4, 4/thread
    auto issue = [&](int stage, int t) {
        int k0 = t * BKT;
        #pragma unroll
        for (int i = 0; i < 4; i++) {
            int v = tid + i * 256;
            int r = v >> 3, c = (v & 7) * 4;
            int gr = rowBase + r, gc = k0 + c;
            unsigned dst = aBase + (unsigned)(stage * BM * ASTRIDE + r * ASTRIDE + c) * 4;
            cp16(dst, A + (size_t)gr * lda + gc, (gr < M && gc < K) ? 16 : 0);
        }
        #pragma unroll
        for (int i = 0; i < 4; i++) {
            int v = tid + i * 256;
            int r = v >> 5, c = (v & 31) * 4;
            int gr = k0 + r, gc = colBase + c;
            unsigned dst = bBase + (unsigned)(stage * BKT * BSTRIDE + r * BSTRIDE + c) * 4;
            cp16(dst, B + (size_t)gr * N + gc, (gr < K && gc < N) ? 16 : 0);
        }
    };

    issue(0, 0);
    asm volatile("cp.async.commit_group;\n");

    for (int t = 0; t < ntiles; t++) {
        asm volatile("cp.async.wait_group 0;\n");
        __syncthreads();
        if (t + 1 < ntiles) issue((t + 1) & 1, t + 1);
        asm volatile("cp.async.commit_group;\n");
        int b = t & 1;
        #pragma unroll
        for (int kk = 0; kk < BKT; kk += 8) {
            unsigned bf[4][2];
            #pragma unroll
            for (int nt = 0; nt < 4; nt++) {
                int n = wn * 32 + nt * 8 + grp;
                bf[nt][0] = __float_as_uint(Bs[b][kk + tig][n]);
                bf[nt][1] = __float_as_uint(Bs[b][kk + tig + 4][n]);
            }
            #pragma unroll
            for (int mt = 0; mt < 4; mt++) {
                int r = wm * 64 + mt * 16 + grp;
                unsigned a0 = __float_as_uint(As[b][r][kk + tig]);
                unsigned a1 = __float_as_uint(As[b][r + 8][kk + tig]);
                unsigned a2 = __float_as_uint(As[b][r][kk + tig + 4]);
                unsigned a3 = __float_as_uint(As[b][r + 8][kk + tig + 4]);
                #pragma unroll
                for (int nt = 0; nt < 4; nt++) {
                    asm volatile(
                        "mma.sync.aligned.m16n8k8.row.col.f32.tf32.tf32.f32 "
                        "{%0,%1,%2,%3}, {%4,%5,%6,%7}, {%8,%9}, {%0,%1,%2,%3};\n"
                        : "+f"(acc[mt][nt][0]), "+f"(acc[mt][nt][1]),
                          "+f"(acc[mt][nt][2]), "+f"(acc[mt][nt][3])
                        : "r"(a0), "r"(a1), "r"(a2), "r"(a3),
                          "r"(bf[nt][0]), "r"(bf[nt][1]));
                }
            }
        }
    }

    #pragma unroll
    for (int mt = 0; mt < 4; mt++) {
        #pragma unroll
        for (int nt = 0; nt < 4; nt++) {
            int r0 = rowBase + wm * 64 + mt * 16 + grp;
            int c0 = colBase + wn * 32 + nt * 8 + tig * 2;
            #pragma unroll
            for (int half = 0; half < 2; half++) {
                int r = r0 + half * 8;
                if (r >= M) continue;
                #pragma unroll
                for (int j = 0; j < 2; j++) {
                    int c = c0 + j;
                    if (c >= N) continue;
                    float v = acc[mt][nt][half * 2 + j];
                    if (bias) v += bias[c];
                    v *= scale_ep;
                    if (leaky) v = leakyf(v);
                    if (rnd) v = rna(v);
                    C[(size_t)r * ldc + c] = v;
                }
            }
        }
    }
}

// generic fallback (unaligned N) — register staging
__global__ __launch_bounds__(256, 2)
void mma_gemm_gen(const float* __restrict__ A, const float* __restrict__ B,
                  float* __restrict__ C, int M, int N, int K, int lda, int ldc,
                  const float* __restrict__ bias, float scale_ep, int leaky)
{
    __shared__ float As[2][BM][20];
    __shared__ float Bs[2][16][BSTRIDE];
    const int tid = threadIdx.x, lane = tid & 31, warp = tid >> 5;
    const int wm = warp & 1, wn = warp >> 1, grp = lane >> 2, tig = lane & 3;
    const int rowBase = blockIdx.y * BM, colBase = blockIdx.x * BN;
    float acc[4][4][4];
    #pragma unroll
    for (int i = 0; i < 4; i++)
        #pragma unroll
        for (int j = 0; j < 4; j++)
            #pragma unroll
            for (int q = 0; q < 4; q++) acc[i][j][q] = 0.f;
    const int ntiles = (K + 15) / 16;
    float aR[2][4], bR[2][4];
    auto loadRegs = [&](int t) {
        int k0 = t * 16;
        #pragma unroll
        for (int i = 0; i < 2; i++) {
            int v = tid + i * 256;
            int r = v >> 2, c = (v & 3) * 4;
            int gr = rowBase + r, gc = k0 + c;
            #pragma unroll
            for (int q = 0; q < 4; q++)
                aR[i][q] = (gr < M && gc + q < K) ? A[(size_t)gr * lda + gc + q] : 0.f;
        }
        #pragma unroll
        for (int i = 0; i < 2; i++) {
            int v = tid + i * 256;
            int r = v >> 5, c = (v & 31) * 4;
            int gr = k0 + r, gc = colBase + c;
            #pragma unroll
            for (int q = 0; q < 4; q++)
                bR[i][q] = (gr < K && gc + q < N) ? B[(size_t)gr * N + gc + q] : 0.f;
        }
    };
    auto stsTile = [&](int b) {
        #pragma unroll
        for (int i = 0; i < 2; i++) {
            int v = tid + i * 256;
            int r = v >> 2, c = (v & 3) * 4;
            #pragma unroll
            for (int q = 0; q < 4; q++) As[b][r][c + q] = aR[i][q];
        }
        #pragma unroll
        for (int i = 0; i < 2; i++) {
            int v = tid + i * 256;
            int r = v >> 5, c = (v & 31) * 4;
            #pragma unroll
            for (int q = 0; q < 4; q++) Bs[b][r][c + q] = bR[i][q];
        }
    };
    loadRegs(0); stsTile(0);
    for (int t = 0; t < ntiles; t++) {
        __syncthreads();
        if (t + 1 < ntiles) loadRegs(t + 1);
        int b = t & 1;
        #pragma unroll
        for (int kk = 0; kk < 16; kk += 8) {
            unsigned bf[4][2];
            #pragma unroll
            for (int nt = 0; nt < 4; nt++) {
                int n = wn * 32 + nt * 8 + grp;
                bf[nt][0] = __float_as_uint(Bs[b][kk + tig][n]);
                bf[nt][1] = __float_as_uint(Bs[b][kk + tig + 4][n]);
            }
            #pragma unroll
            for (int mt = 0; mt < 4; mt++) {
                int r = wm * 64 + mt * 16 + grp;
                unsigned a0 = __float_as_uint(As[b][r][kk + tig]);
                unsigned a1 = __float_as_uint(As[b][r + 8][kk + tig]);
                unsigned a2 = __float_as_uint(As[b][r][kk + tig + 4]);
                unsigned a3 = __float_as_uint(As[b][r + 8][kk + tig + 4]);
                #pragma unroll
                for (int nt = 0; nt < 4; nt++) {
                    asm volatile(
                        "mma.sync.aligned.m16n8k8.row.col.f32.tf32.tf32.f32 "
                        "{%0,%1,%2,%3}, {%4,%5,%6,%7}, {%8,%9}, {%0,%1,%2,%3};\n"
                        : "+f"(acc[mt][nt][0]), "+f"(acc[mt][nt][1]),
                          "+f"(acc[mt][nt][2]), "+f"(acc[mt][nt][3])
                        : "r"(a0), "r"(a1), "r"(a2), "r"(a3),
                          "r"(bf[nt][0]), "r"(bf[nt][1]));
                }
            }
        }
        if (t + 1 < ntiles) stsTile((t + 1) & 1);
    }
    #pragma unroll
    for (int mt = 0; mt < 4; mt++)
        #pragma unroll
        for (int nt = 0; nt < 4; nt++) {
            int r0 = rowBase + wm * 64 + mt * 16 + grp;
            int c0 = colBase + wn * 32 + nt * 8 + tig * 2;
            #pragma unroll
            for (int half = 0; half < 2; half++) {
                int r = r0 + half * 8;
                if (r >= M) continue;
                #pragma unroll
                for (int j = 0; j < 2; j++) {
                    int c = c0 + j;
                    if (c >= N) continue;
                    float v = acc[mt][nt][half * 2 + j];
                    if (bias) v += bias[c];
                    v *= scale_ep;
                    if (leaky) v = leakyf(v);
                    C[(size_t)r * ldc + c] = v;
                }
            }
        }
}

// ---------------------------- CSR build kernels ----------------------------
__global__ void hist_kernel(const int* __restrict__ dst, int* __restrict__ cnt, int n)
{
    int e = blockIdx.x * 256 + threadIdx.x;
    if (e < n) atomicAdd(&cnt[dst[e]], 1);
}

// single-block chunked exclusive scan; off has n+1 entries
__global__ void scan_kernel(const int* __restrict__ cnt, int* __restrict__ off, int n)
{
    __shared__ int sm[1024];
    __shared__ int carry;
    if (threadIdx.x == 0) carry = 0;
    __syncthreads();
    for (int base = 0; base < n; base += 1024) {
        int i = base + threadIdx.x;
        int v = (i < n) ? cnt[i] : 0;
        sm[threadIdx.x] = v;
        __syncthreads();
        for (int o = 1; o < 1024; o <<= 1) {
            int t = (threadIdx.x >= o) ? sm[threadIdx.x - o] : 0;
            __syncthreads();
            sm[threadIdx.x] += t;
            __syncthreads();
        }
        if (i < n) off[i] = carry + sm[threadIdx.x] - v;
        __syncthreads();
        if (threadIdx.x == 1023) carry += sm[1023];
        __syncthreads();
    }
    if (threadIdx.x == 0) off[n] = carry;
}

__global__ void place_kernel(const int* __restrict__ src, const int* __restrict__ dst,
                             const int* __restrict__ ij, const int* __restrict__ off,
                             int* __restrict__ cur, int* __restrict__ psrc,
                             int* __restrict__ pij, int n)
{
    int e = blockIdx.x * 256 + threadIdx.x;
    if (e >= n) return;
    int d = dst[e];
    int p = off[d] + atomicAdd(&cur[d], 1);
    psrc[p] = src[e];
    if (pij) pij[p] = ij[e];
}

// ---------------------------- aggregation kernels ----------------------------
__global__ __launch_bounds__(128)
void agg_win_kernel(const int* __restrict__ off, const int* __restrict__ psrc,
                    const int* __restrict__ pij, const float4* __restrict__ wcat,
                    const float4* __restrict__ ecat, float* __restrict__ outBase)
{
    int d = blockIdx.x;
    int s0 = off[d], s1 = off[d + 1];
    int c = threadIdx.x;
    float4 acc = make_float4(0.f, 0.f, 0.f, 0.f);
    for (int k = s0; k < s1; k++) {
        float4 a = wcat[(size_t)psrc[k] * (WCAT / 4) + c];
        float4 b = ecat[(size_t)pij[k] * (ECAT / 4) + c];
        acc.x += a.x + b.x; acc.y += a.y + b.y;
        acc.z += a.z + b.z; acc.w += a.w + b.w;
    }
    float rc = 1.f / fmaxf((float)(s1 - s0), 1.f);
    float4 o = make_float4(rna(acc.x * rc), rna(acc.y * rc),
                           rna(acc.z * rc), rna(acc.w * rc));
    *(float4*)(outBase + (size_t)d * WCAT + (c << 2)) = o;
}

__global__ __launch_bounds__(128)
void agg_edge_kernel(const int* __restrict__ off, const int* __restrict__ psrc,
                     const float4* __restrict__ ecat, float* __restrict__ outBase)
{
    int d = blockIdx.x;
    int s0 = off[d], s1 = off[d + 1];
    int c = threadIdx.x;
    float4 acc = make_float4(0.f, 0.f, 0.f, 0.f);
    for (int k = s0; k < s1; k++) {
        float4 a = ecat[(size_t)psrc[k] * (ECAT / 4) + c];
        acc.x += a.x; acc.y += a.y; acc.z += a.z; acc.w += a.w;
    }
    float rc = 1.f / fmaxf((float)(s1 - s0), 1.f);
    float4 o = make_float4(rna(acc.x * rc), rna(acc.y * rc),
                           rna(acc.z * rc), rna(acc.w * rc));
    *(float4*)(outBase + (size_t)d * ECAT + (c << 2)) = o;
}

// ---------------------------- small kernels ----------------------------
__global__ void padx_kernel(const float* __restrict__ x, float* __restrict__ xp)
{
    size_t idx = (size_t)blockIdx.x * blockDim.x + threadIdx.x;
    if (idx >= (size_t)NE * ECHP) return;
    int r = (int)(idx / ECHP), c = (int)(idx % ECHP);
    xp[idx] = (c < ECH) ? rna(x[(size_t)r * ECH + c]) : 0.f;
}

__global__ void padw_kernel(const float* __restrict__ w, float* __restrict__ wp)
{
    size_t idx = (size_t)blockIdx.x * blockDim.x + threadIdx.x;
    if (idx >= (size_t)ECHP * H) return;
    int r = (int)(idx / H);
    wp[idx] = (r < ECH) ? rna(w[idx]) : 0.f;
}

__global__ void rcopy_kernel(const float* __restrict__ in, float* __restrict__ out, size_t n)
{
    size_t idx = (size_t)blockIdx.x * blockDim.x + threadIdx.x;
    if (idx < n) out[idx] = rna(in[idx]);
}

__global__ void rowdot_kernel(const float* __restrict__ W, const float* __restrict__ v,
                              float* __restrict__ out)
{
    int row = (blockIdx.x * blockDim.x + threadIdx.x) >> 5;
    int lane = threadIdx.x & 31;
    if (row >= H) return;
    const float* p = W + (size_t)row * H;
    float acc = 0.f;
    for (int j = lane; j < H; j += 32) acc += p[j] * v[j];
    #pragma unroll
    for (int o = 16; o > 0; o >>= 1) acc += __shfl_down_sync(0xffffffffu, acc, o);
    if (!lane) out[row] = acc;
}

__global__ void vecmat_kernel(const float* __restrict__ x, const float* __restrict__ W,
                              const float* __restrict__ bias, float* __restrict__ out)
{
    int j = blockIdx.x * blockDim.x + threadIdx.x;
    if (j >= H) return;
    float acc = bias ? bias[j] : 0.f;
    for (int k = 0; k < H; k++) acc += x[k] * W[(size_t)k * H + j];
    out[j] = acc;
}

__global__ void scores_kernel(const float* __restrict__ hw, int lda,
                              const float* __restrict__ w, float* __restrict__ s,
                              float scale)
{
    int row = (blockIdx.x * blockDim.x + threadIdx.x) >> 5;
    int lane = threadIdx.x & 31;
    if (row >= NW) return;
    const float* p = hw + (size_t)row * lda;
    float acc = 0.f;
    for (int c = lane; c < H; c += 32) acc += p[c] * w[c];
    #pragma unroll
    for (int o = 16; o > 0; o >>= 1) acc += __shfl_down_sync(0xffffffffu, acc, o);
    if (!lane) s[row] = acc * scale;
}

__global__ void rmax_part(const float* __restrict__ s, int n, float* __restrict__ part)
{
    __shared__ float sm[256];
    float m = -3.4e38f;
    for (int i = blockIdx.x * 256 + threadIdx.x; i < n; i += gridDim.x * 256)
        m = fmaxf(m, s[i]);
    sm[threadIdx.x] = m; __syncthreads();
    for (int o = 128; o > 0; o >>= 1) {
        if (threadIdx.x < o) sm[threadIdx.x] = fmaxf(sm[threadIdx.x], sm[threadIdx.x + o]);
        __syncthreads();
    }
    if (!threadIdx.x) part[blockIdx.x] = sm[0];
}

__global__ void rmax_final(const float* __restrict__ part, int nb, float* __restrict__ out)
{
    __shared__ float sm[256];
    sm[threadIdx.x] = (threadIdx.x < nb) ? part[threadIdx.x] : -3.4e38f;
    __syncthreads();
    for (int o = 128; o > 0; o >>= 1) {
        if (threadIdx.x < o) sm[threadIdx.x] = fmaxf(sm[threadIdx.x], sm[threadIdx.x + o]);
        __syncthreads();
    }
    if (!threadIdx.x) out[0] = sm[0];
}

__global__ void exp_part(float* __restrict__ s, const float* __restrict__ mx, int n,
                         float* __restrict__ part)
{
    __shared__ float sm[256];
    float m = mx[0];
    float acc = 0.f;
    for (int i = blockIdx.x * 256 + threadIdx.x; i < n; i += gridDim.x * 256) {
        float e = expf(s[i] - m);
        s[i] = e;
        acc += e;
    }
    sm[threadIdx.x] = acc; __syncthreads();
    for (int o = 128; o > 0; o >>= 1) {
        if (threadIdx.x < o) sm[threadIdx.x] += sm[threadIdx.x + o];
        __syncthreads();
    }
    if (!threadIdx.x) part[blockIdx.x] = sm[0];
}

__global__ void rsum_final(const float* __restrict__ part, int nb, float* __restrict__ out)
{
    __shared__ float sm[256];
    sm[threadIdx.x] = (threadIdx.x < nb) ? part[threadIdx.x] : 0.f;
    __syncthreads();
    for (int o = 128; o > 0; o >>= 1) {
        if (threadIdx.x < o) sm[threadIdx.x] += sm[threadIdx.x + o];
        __syncthreads();
    }
    if (!threadIdx.x) out[0] = sm[0];
}

__global__ void attnv_kernel(const float* __restrict__ hw, int lda,
                             const float* __restrict__ w, const float* __restrict__ sum,
                             float* __restrict__ out, int n)
{
    int c = blockIdx.x * 256 + threadIdx.x;
    int chunk = (n + gridDim.y - 1) / gridDim.y;
    int r0 = blockIdx.y * chunk;
    int r1 = min(r0 + chunk, n);
    float acc = 0.f;
    for (int r = r0; r < r1; r++) acc += w[r] * hw[(size_t)r * lda + c];
    atomicAdd(&out[c], acc / sum[0]);
}

__global__ void build_bw_kernel(const float* __restrict__ Wl, const float* __restrict__ Wr,
                                float* __restrict__ out)
{
    size_t idx = (size_t)blockIdx.x * blockDim.x + threadIdx.x;
    if (idx >= (size_t)WCAT * H) return;
    int row = (int)(idx / H), j = (int)(idx % H);
    float v;
    if (row < H) {
        v = Wr[(size_t)row * H + j] + Wr[(size_t)(H + row) * H + j]
          + Wr[(size_t)(2 * H + row) * H + j];
    } else {
        v = Wl[(size_t)(row - H) * H + j];
    }
    out[idx] = rna(v);
}

__global__ void build_be_kernel(const float* __restrict__ Wl, const float* __restrict__ Wr,
                                float* __restrict__ out)
{
    size_t idx = (size_t)blockIdx.x * blockDim.x + threadIdx.x;
    if (idx >= (size_t)ECAT * H) return;
    int row = (int)(idx / H), j = (int)(idx % H);
    out[idx] = rna((row < H) ? Wr[(size_t)row * H + j] : Wl[(size_t)(row - H) * H + j]);
}

__global__ void matsum3_kernel(const float* __restrict__ a, const float* __restrict__ b,
                               const float* __restrict__ c, float* __restrict__ o, int n)
{
    int i = blockIdx.x * 256 + threadIdx.x;
    if (i < n) o[i] = a[i] + b[i] + c[i];
}

__global__ void bs2_kernel(const float* __restrict__ gs, const float* __restrict__ b,
                           float* __restrict__ out)
{
    int i = blockIdx.x * 256 + threadIdx.x;
    if (i < H) out[i] = gs[i] + b[i] + b[H + i] + b[2 * H + i];
}

// ------------------------------- host orchestration -------------------------------
static void gemmA(const float* A, const float* B, float* C, int M, int N, int K,
                  int lda, int ldc, const float* bias, float scale, int leaky, int rnd)
{
    dim3 grid((N + BN - 1) / BN, (M + BM - 1) / BM);
    mma_gemm_async<<<grid, 256, GEMM_SMEM>>>(A, B, C, M, N, K, lda, ldc,
                                             bias, scale, leaky, rnd);
}

static void gemmG(const float* A, const float* B, float* C, int M, int N, int K,
                  int lda, int ldc, const float* bias, float scale, int leaky)
{
    dim3 grid((N + BN - 1) / BN, (M + BM - 1) / BM);
    mma_gemm_gen<<<grid, 256>>>(A, B, C, M, N, K, lda, ldc, bias, scale, leaky);
}

extern "C" void kernel_launch(void* const* d_in, const int* in_sizes, int n_in,
                              void* d_out, int out_size)
{
    const float* x_win       = (const float*)d_in[0];
    const float* x_edge      = (const float*)d_in[1];
    const float* W_pre_win   = (const float*)d_in[2];
    const float* W_post_win  = (const float*)d_in[3];
    const float* W_pre_edge  = (const float*)d_in[4];
    const float* W_post_edge = (const float*)d_in[5];
    const float* conv_Wl     = (const float*)d_in[6];
    const float* conv_Wr     = (const float*)d_in[7];
    const float* conv_Wg     = (const float*)d_in[8];
    const float* conv_b      = (const float*)d_in[9];
    const float* econv_Wl    = (const float*)d_in[10];
    const float* econv_Wr    = (const float*)d_in[11];
    const float* econv_b     = (const float*)d_in[12];
    const float* pool_lin1_W = (const float*)d_in[13];
    const float* pool_lin1_b = (const float*)d_in[14];
    const float* pool_S      = (const float*)d_in[15];
    const float* pool_Wq     = (const float*)d_in[16];
    const float* pool_Wk     = (const float*)d_in[17];
    const float* pool_Wv     = (const float*)d_in[18];
    const float* pool_lin2_W = (const float*)d_in[19];
    const float* pool_lin2_b = (const float*)d_in[20];
    const float* lin_W       = (const float*)d_in[21];
    const float* lin_b       = (const float*)d_in[22];
    const int* ein = (const int*)d_in[23];
    const int* eic = (const int*)d_in[24];
    const int* eis = (const int*)d_in[25];
    const int* ijn = (const int*)d_in[26];
    const int* ijc = (const int*)d_in[27];
    const int* ijs = (const int*)d_in[28];
    const int* eee = (const int*)d_in[29];

    static int smemSet = 0;
    if (!smemSet) {
        cudaFuncSetAttribute(mma_gemm_async, cudaFuncAttributeMaxDynamicSharedMemorySize,
                             GEMM_SMEM);
        smemSet = 1;
    }

    float *wcatA, *wcatB, *ecatA, *ecatB, *xpad, *wpad, *tmp, *Bw, *Be;
    float *sbuf, *part, *stat, *vec, *bs2, *Wgsum;
    int *cnti, *cur, *offw, *offe, *psrcw, *pijw, *psrce;
    cudaGetSymbolAddress((void**)&wcatA, g_wcatA);
    cudaGetSymbolAddress((void**)&wcatB, g_wcatB);
    cudaGetSymbolAddress((void**)&ecatA, g_ecatA);
    cudaGetSymbolAddress((void**)&ecatB, g_ecatB);
    cudaGetSymbolAddress((void**)&xpad,  g_xpad);
    cudaGetSymbolAddress((void**)&wpad,  g_wpad);
    cudaGetSymbolAddress((void**)&tmp,   g_tmp);
    cudaGetSymbolAddress((void**)&Bw,    g_Bw);
    cudaGetSymbolAddress((void**)&Be,    g_Be);
    cudaGetSymbolAddress((void**)&sbuf,  g_s);
    cudaGetSymbolAddress((void**)&part,  g_part);
    cudaGetSymbolAddress((void**)&stat,  g_stat);
    cudaGetSymbolAddress((void**)&vec,   g_vec);
    cudaGetSymbolAddress((void**)&bs2,   g_bs2);
    cudaGetSymbolAddress((void**)&Wgsum, g_Wgsum);
    cudaGetSymbolAddress((void**)&cnti,  g_cnti);
    cudaGetSymbolAddress((void**)&cur,   g_cur);
    cudaGetSymbolAddress((void**)&offw,  g_offw);
    cudaGetSymbolAddress((void**)&offe,  g_offe);
    cudaGetSymbolAddress((void**)&psrcw, g_psrcw);
    cudaGetSymbolAddress((void**)&pijw,  g_pijw);
    cudaGetSymbolAddress((void**)&psrce, g_psrce);

    float* qv   = vec;
    float* wk   = vec + H;
    float* wfin = vec + 2 * H;
    float* u    = vec + 3 * H;
    float* h1u  = vec + 4 * H;
    float* gv0  = vec + 5 * H;
    float* gvec = vec + 6 * H;
    float* gs   = vec + 7 * H;

    const int* srcs[NREL] = {ein, eic, eis};
    const int* ijx[NREL]  = {ijn, ijc, ijs};

    // ---- CSR build (per launch) ----
    for (int r = 0; r < NREL; r++) {
        cudaMemsetAsync(cnti, 0, NW * sizeof(int));
        hist_kernel<<<(ER + 255) / 256, 256>>>(srcs[r] + ER, cnti, ER);
        scan_kernel<<<1, 1024>>>(cnti, offw + r * (NW + 1), NW);
        cudaMemsetAsync(cur, 0, NW * sizeof(int));
        place_kernel<<<(ER + 255) / 256, 256>>>(srcs[r], srcs[r] + ER, ijx[r],
                                                offw + r * (NW + 1), cur,
                                                psrcw + (size_t)r * ER,
                                                pijw + (size_t)r * ER, ER);
    }
    cudaMemsetAsync(cnti, 0, NE * sizeof(int));
    hist_kernel<<<(EE + 255) / 256, 256>>>(eee + EE, cnti, EE);
    scan_kernel<<<1, 1024>>>(cnti, offe, NE);
    cudaMemsetAsync(cur, 0, NE * sizeof(int));
    place_kernel<<<(EE + 255) / 256, 256>>>(eee, eee + EE, nullptr, offe, cur,
                                            psrce, nullptr, EE);

    // ---- rounded operand staging ----
    padx_kernel<<<(int)(((size_t)NE * ECHP + 255) / 256), 256>>>(x_edge, xpad);
    padw_kernel<<<(int)(((size_t)ECHP * H + 255) / 256), 256>>>(W_pre_edge, wpad);
    rcopy_kernel<<<(int)(((size_t)NW * MDIM + 255) / 256), 256>>>(
        x_win, wcatB, (size_t)NW * MDIM);                       // x_win rounded (contig)
    rcopy_kernel<<<(H * H + 255) / 256, 256>>>(W_pre_win, Wgsum, (size_t)H * H);
    rcopy_kernel<<<(H * H + 255) / 256, 256>>>(W_post_win, Bw, (size_t)H * H);
    rcopy_kernel<<<(H * H + 255) / 256, 256>>>(W_post_edge, Be, (size_t)H * H);

    // ---- pretransforms ----
    gemmA(wcatB, Wgsum, tmp, NW, H, MDIM, MDIM, H, nullptr, 1.f, 1, 1);
    gemmA(tmp, Bw, wcatA, NW, H, H, H, WCAT, nullptr, 1.f, 1, 1);
    gemmA(xpad, wpad, tmp, NE, H, ECHP, ECHP, H, nullptr, 1.f, 1, 1);
    gemmA(tmp, Be, ecatA, NE, H, H, H, ECAT, nullptr, 1.f, 1, 1);

    float* wA = wcatA; float* wB = wcatB;
    float* eA = ecatA; float* eB = ecatB;
    const float scale = 1.f / sqrtf((float)H);

    for (int l = 0; l < NLAYER; l++) {
        size_t wOff = (size_t)l * H * H;
        size_t wb   = (size_t)l * NREL * H * H;
        size_t bb   = (size_t)l * NREL * H;

        // ---- pooling (algebraically reduced) ----
        vecmat_kernel<<<2, 256>>>(pool_S + (size_t)l * H, pool_Wq + wOff, nullptr, qv);
        rowdot_kernel<<<64, 256>>>(pool_Wk + wOff, qv, wk);
        rowdot_kernel<<<64, 256>>>(pool_lin1_W + wOff, wk, wfin);
        scores_kernel<<<(NW * 32 + 255) / 256, 256>>>(wA, WCAT, wfin, sbuf, scale);
        rmax_part<<<240, 256>>>(sbuf, NW, part);
        rmax_final<<<1, 256>>>(part, 240, stat);
        exp_part<<<240, 256>>>(sbuf, stat, NW, part);
        rsum_final<<<1, 256>>>(part, 240, stat + 1);
        cudaMemsetAsync(u, 0, H * sizeof(float));
        {
            dim3 ag(H / 256, 79);
            attnv_kernel<<<ag, 256>>>(wA, WCAT, sbuf, stat + 1, u, NW);
        }
        vecmat_kernel<<<2, 256>>>(u, pool_lin1_W + wOff, pool_lin1_b + (size_t)l * H, h1u);
        vecmat_kernel<<<2, 256>>>(h1u, pool_Wv + wOff, nullptr, gv0);
        vecmat_kernel<<<2, 256>>>(gv0, pool_lin2_W + wOff, pool_lin2_b + (size_t)l * H, gvec);
        matsum3_kernel<<<(H * H + 255) / 256, 256>>>(
            conv_Wg + wb, conv_Wg + wb + (size_t)H * H, conv_Wg + wb + 2 * (size_t)H * H,
            Wgsum, H * H);
        vecmat_kernel<<<2, 256>>>(gvec, Wgsum, nullptr, gs);
        bs2_kernel<<<2, 256>>>(gs, conv_b + bb, bs2);

        // ---- weights concat (rounded) ----
        build_bw_kernel<<<(int)(((size_t)WCAT * H + 255) / 256), 256>>>(
            conv_Wl + wb, conv_Wr + wb, Bw);
        build_be_kernel<<<(int)(((size_t)ECAT * H + 255) / 256), 256>>>(
            econv_Wl + wOff, econv_Wr + wOff, Be);

        // ---- CSR aggregation (mean + rounding folded in) ----
        for (int r = 0; r < NREL; r++) {
            agg_win_kernel<<<NW, 128>>>(offw + r * (NW + 1),
                                        psrcw + (size_t)r * ER, pijw + (size_t)r * ER,
                                        (const float4*)wA, (const float4*)eA,
                                        wA + (size_t)(1 + r) * H);
        }
        agg_edge_kernel<<<NE, 128>>>(offe, psrce, (const float4*)eA, eA + H);

        // ---- fused conv GEMMs ----
        gemmA(wA, Bw, wB, NW, H, WCAT, WCAT, WCAT, bs2, 1.f / (float)NREL, 1, 1);
        gemmA(eA, Be, eB, NE, H, ECAT, ECAT, ECAT, econv_b + (size_t)l * H, 1.f, 1, 1);

        float* t = wA; wA = wB; wB = t;
        t = eA; eA = eB; eB = t;
    }

    // ---- final linear (N=250 unaligned -> generic, no rounding on output) ----
    gemmG(wA, lin_W, (float*)d_out, NW, OUT_DIM, H, WCAT, OUT_DIM, lin_b, 1.f, 0);
}